// round 12
// baseline (speedup 1.0000x reference)
#include <cuda_runtime.h>
#include <cuda_fp16.h>
#include <cstdint>

// ---------------- problem constants ----------------
#define D_      256
#define B_      4
#define M_      64
#define N_      512
#define H_      8
#define F_      1024
#define ROWS_M  256        // B*M
#define ROWS_O  2048       // B*N
#define NEDGE   131072     // B*N*M
#define SCALE_  0.17677669529663687f   // 1/sqrt(32)
#define EPS_    1e-5f
#define BIG_NEG (-1e30f)

#define FLAG_RELU    1
#define FLAG_SPLIT   4
#define FLAG_HALFOUT 8

// ---------------- scratch (device globals; no runtime allocation) ----------------
__device__ __align__(16) __half g_mnorm16[ROWS_M * D_];
__device__ __align__(16) __half g_onorm16[ROWS_O * D_];
__device__ __align__(16) __half g_Wqkv16[D_ * 768];
__device__ __align__(16) __half g_Wkv16 [D_ * 512];
__device__ __align__(16) __half g_We16  [D_ * D_];
__device__ __align__(16) __half g_Wf1_16[D_ * F_];
__device__ __align__(16) __half g_Wf2_16[F_ * D_];
__device__ __align__(16) __half g_f1h   [ROWS_M * F_];
__device__ __align__(16) __half g_h16   [ROWS_M * D_];
__device__ __align__(16) __half g_kvh   [ROWS_O * 512];      // 0:256 k | 256:512 v (fp16)
__device__ __align__(16) __half g_Eh    [(size_t)NEDGE * D_];// compacted projected edges fp16
__device__ float g_bqkv[768];
__device__ float g_bkv [512];
__device__ float g_qkv [ROWS_M * 768];        // 0:256 q | 256:512 ks | 512:768 vs
__device__ float g_me2 [ROWS_M * D_];
__device__ float g_f2part[4 * ROWS_M * D_];
__device__ int   g_actN[ROWS_M * N_];
__device__ int   g_actCnt[ROWS_M];
__device__ int   g_rowStart[ROWS_M + 1];
__device__ int   g_rowIdx[NEDGE];
__device__ int   g_count;
__device__ int   g_flagGt1, g_flagNz;

// ---------------- helpers ----------------
__device__ __forceinline__ float warpSum(float v) {
#pragma unroll
    for (int o = 16; o; o >>= 1) v += __shfl_xor_sync(0xffffffffu, v, o);
    return v;
}
__device__ __forceinline__ uint32_t packh2(float x, float y) {
    __half2 h = __floats2half2_rn(x, y);
    return *reinterpret_cast<uint32_t*>(&h);
}
__device__ __forceinline__ uint32_t smemAddr(const void* p) {
    return (uint32_t)__cvta_generic_to_shared(p);
}

#define CP16(d, s) asm volatile("cp.async.ca.shared.global [%0], [%1], 16;" :: "r"(d), "l"(s))
#define CPCOMMIT() asm volatile("cp.async.commit_group;")
#define CPWAIT0()  asm volatile("cp.async.wait_group 0;")
#define CPWAIT1()  asm volatile("cp.async.wait_group 1;")

#define LDSM4(r, addr)                                                          \
    asm volatile("ldmatrix.sync.aligned.m8n8.x4.shared.b16 {%0,%1,%2,%3}, [%4];"\
                 : "=r"((r)[0]), "=r"((r)[1]), "=r"((r)[2]), "=r"((r)[3])       \
                 : "r"(addr))
#define LDSM4T(r, addr)                                                         \
    asm volatile("ldmatrix.sync.aligned.m8n8.x4.trans.shared.b16 {%0,%1,%2,%3}, [%4];" \
                 : "=r"((r)[0]), "=r"((r)[1]), "=r"((r)[2]), "=r"((r)[3])       \
                 : "r"(addr))
#define MMA16816(d, a, b0v, b1v)                                                \
    asm volatile("mma.sync.aligned.m16n8k16.row.col.f32.f16.f16.f32 "           \
                 "{%0,%1,%2,%3},{%4,%5,%6,%7},{%8,%9},{%0,%1,%2,%3};"           \
                 : "+f"((d)[0]), "+f"((d)[1]), "+f"((d)[2]), "+f"((d)[3])       \
                 : "r"((a)[0]), "r"((a)[1]), "r"((a)[2]), "r"((a)[3]),          \
                   "r"(b0v), "r"(b1v))

// ---------------- mask preprocessing ----------------
__global__ void detect_kernel(const unsigned char* __restrict__ p, int nbytes) {
    int i = blockIdx.x * blockDim.x + threadIdx.x;
    int stride = gridDim.x * blockDim.x;
    int gt1 = 0, nz = 0;
    for (; i < nbytes; i += stride) {
        unsigned char v = p[i];
        gt1 |= (v > 1);
        nz  |= (v != 0 && (i & 3) != 0);
    }
    if (__any_sync(0xffffffffu, gt1) && (threadIdx.x & 31) == 0) atomicOr(&g_flagGt1, 1);
    if (__any_sync(0xffffffffu, nz)  && (threadIdx.x & 31) == 0) atomicOr(&g_flagNz, 1);
}

__global__ void actlist_kernel(const void* __restrict__ mask) {
    int wid = threadIdx.x >> 5, lane = threadIdx.x & 31;
    int row = blockIdx.x * 8 + wid;
    int b = row >> 6, m = row & 63;
    int mode = g_flagGt1 ? 2 : (g_flagNz ? 1 : 0);
    int base = 0;
#pragma unroll 1
    for (int c = 0; c < 16; c++) {
        int n = c * 32 + lane;
        size_t mi = ((size_t)(b * N_ + n)) * M_ + m;
        bool a;
        if (mode == 2)      a = ((const float*)mask)[mi] != 0.0f;
        else if (mode == 1) a = ((const unsigned char*)mask)[mi] != 0;
        else                a = ((const int*)mask)[mi] != 0;
        unsigned bal = __ballot_sync(0xffffffffu, a);
        if (a) g_actN[row * N_ + base + __popc(bal & ((1u << lane) - 1u))] = n;
        base += __popc(bal);
    }
    if (lane == 0) g_actCnt[row] = base;
}

// Merged prefix + fill; resets mask flags for next replay.
__global__ void prefixfill_kernel() {
    __shared__ int ws[8];
    __shared__ int startS;
    int tid = threadIdx.x;
    int row = blockIdx.x;
    int v = g_actCnt[tid];
    int lane = tid & 31, w = tid >> 5;
    int inc = v;
#pragma unroll
    for (int o = 1; o < 32; o <<= 1) {
        int t = __shfl_up_sync(0xffffffffu, inc, o);
        if (lane >= o) inc += t;
    }
    if (lane == 31) ws[w] = inc;
    __syncthreads();
    int add = 0;
#pragma unroll
    for (int i = 0; i < 8; i++) if (i < w) add += ws[i];
    int excl = inc - v + add;
    if (row == 0) {
        g_rowStart[tid] = excl;
        if (tid == 255) { g_rowStart[256] = excl + v; g_count = excl + v; }
        if (tid == 0) { g_flagGt1 = 0; g_flagNz = 0; }
    }
    if (tid == row) startS = excl;
    __syncthreads();
    int myStart = startS;
    int myCnt = g_actCnt[row];
    int b = row >> 6, m = row & 63;
    for (int i = tid; i < myCnt; i += 256) {
        int n = g_actN[row * N_ + i];
        g_rowIdx[myStart + i] = (b * N_ + n) * M_ + m;
    }
}

// ---------------- weight packing -> fp16 ----------------
__global__ void pack_kernel(const float* __restrict__ Wq,  const float* __restrict__ bq,
                            const float* __restrict__ Wks, const float* __restrict__ bks,
                            const float* __restrict__ Wvs, const float* __restrict__ bvs,
                            const float* __restrict__ Wk,  const float* __restrict__ bk,
                            const float* __restrict__ Wv,  const float* __restrict__ bv,
                            const float* __restrict__ Wf1, const float* __restrict__ Wf2,
                            const float* __restrict__ We) {
    int stride = gridDim.x * blockDim.x;
    int i0 = blockIdx.x * blockDim.x + threadIdx.x;
    for (int i = i0; i < D_ * 768; i += stride) {
        int k = i / 768, c = i % 768;
        float v = (c < 256) ? Wq[k * 256 + c]
                : (c < 512) ? Wks[k * 256 + c - 256]
                            : Wvs[k * 256 + c - 512];
        g_Wqkv16[i] = __float2half(v);
    }
    for (int i = i0; i < D_ * 512; i += stride) {
        int k = i / 512, c = i % 512;
        g_Wkv16[i] = __float2half((c < 256) ? Wk[k * 256 + c] : Wv[k * 256 + c - 256]);
    }
    for (int i = i0; i < D_ * F_; i += stride) g_Wf1_16[i] = __float2half(Wf1[i]);
    for (int i = i0; i < F_ * D_; i += stride) g_Wf2_16[i] = __float2half(Wf2[i]);
    for (int i = i0; i < D_ * D_; i += stride) g_We16[i]  = __float2half(We[i]);
    if (i0 < 768)
        g_bqkv[i0] = (i0 < 256) ? bq[i0] : (i0 < 512) ? bks[i0 - 256] : bvs[i0 - 512];
    if (i0 < 512)
        g_bkv[i0] = (i0 < 256) ? bk[i0] : bv[i0 - 256];
}

// ---------------- layernorm (fp32 in -> fp16 out) ----------------
__global__ void ln_kernel(const float* __restrict__ x, const float* __restrict__ g,
                          const float* __restrict__ beta, __half* __restrict__ y) {
    __shared__ float red[16];
    int row = blockIdx.x;
    int tid = threadIdx.x;
    float v = x[(size_t)row * D_ + tid];
    float s  = warpSum(v);
    float s2 = warpSum(v * v);
    if ((tid & 31) == 0) { red[tid >> 5] = s; red[8 + (tid >> 5)] = s2; }
    __syncthreads();
    float sum = 0.f, sum2 = 0.f;
#pragma unroll
    for (int i = 0; i < 8; i++) { sum += red[i]; sum2 += red[8 + i]; }
    float mu  = sum * (1.0f / D_);
    float var = sum2 * (1.0f / D_) - mu * mu;
    float inv = rsqrtf(var + EPS_);
    y[(size_t)row * D_ + tid] = __float2half((v - mu) * inv * g[tid] + beta[tid]);
}

// ---------------- fp16/fp16 GEMM, cp.async 3-stage: 128x128 tile, 8 warps ----------
__global__ __launch_bounds__(256)
void gemm_h(const __half* __restrict__ A, const __half* __restrict__ W,
            const float* __restrict__ bias, float* __restrict__ C,
            __half* __restrict__ Ch,
            int K, int N, int kChunk, int partStride, int flags) {
    __shared__ __align__(16) __half A_sh[3][128][40];
    __shared__ __align__(16) __half B_sh[3][32][136];

    int tid = threadIdx.x;
    int r0 = blockIdx.x * 128, n0 = blockIdx.y * 128;
    int kb0 = blockIdx.z * kChunk;
    float* Cout = C + (size_t)blockIdx.z * partStride;

    int a1 = tid, a2 = tid + 256;
    int aR1 = a1 >> 2, aC1 = a1 & 3, aR2 = a2 >> 2, aC2 = a2 & 3;
    const __half* aS1 = A + (size_t)(r0 + aR1) * K + kb0 + aC1 * 8;
    const __half* aS2 = A + (size_t)(r0 + aR2) * K + kb0 + aC2 * 8;
    uint32_t aD1 = smemAddr(&A_sh[0][aR1][aC1 * 8]);
    uint32_t aD2 = smemAddr(&A_sh[0][aR2][aC2 * 8]);
    int bR1 = tid >> 4, bC = tid & 15, bR2 = bR1 + 16;
    const __half* bS1 = W + (size_t)(kb0 + bR1) * N + n0 + bC * 8;
    const __half* bS2 = W + (size_t)(kb0 + bR2) * N + n0 + bC * 8;
    uint32_t bD1 = smemAddr(&B_sh[0][bR1][bC * 8]);
    uint32_t bD2 = smemAddr(&B_sh[0][bR2][bC * 8]);
    const int ABUF = 128 * 40 * 2, BBUF = 32 * 136 * 2;

#define ISSUE(st, koff)                                                         \
    do {                                                                        \
        CP16(aD1 + (st) * ABUF, aS1 + (koff));                                  \
        CP16(aD2 + (st) * ABUF, aS2 + (koff));                                  \
        CP16(bD1 + (st) * BBUF, bS1 + (size_t)(koff) * N);                      \
        CP16(bD2 + (st) * BBUF, bS2 + (size_t)(koff) * N);                      \
    } while (0)

    float acc[2][8][4];
#pragma unroll
    for (int i = 0; i < 2; i++)
#pragma unroll
        for (int j = 0; j < 8; j++)
#pragma unroll
            for (int l = 0; l < 4; l++) acc[i][j][l] = 0.0f;

    int wid = tid >> 5, lane = tid & 31;
    int wm = wid & 3, wn = wid >> 2;
    int lrow = lane & 15, lcol = lane >> 4;
    uint32_t aLd = smemAddr(&A_sh[0][wm * 32 + lrow][lcol * 8]);
    uint32_t bLd = smemAddr(&B_sh[0][lrow][wn * 64 + lcol * 8]);

    int nIter = kChunk / 32;
    ISSUE(0, 0);
    CPCOMMIT();
    if (nIter > 1) ISSUE(1, 32);
    CPCOMMIT();

#pragma unroll 1
    for (int it = 0; it < nIter; it++) {
        CPWAIT1();
        __syncthreads();
        int st = it % 3;
        int nx = it + 2;
        if (nx < nIter) ISSUE(nx % 3, nx * 32);
        CPCOMMIT();
        uint32_t aB = aLd + st * ABUF;
        uint32_t bB = bLd + st * BBUF;
#pragma unroll
        for (int ks = 0; ks < 2; ks++) {
            uint32_t af[2][4];
#pragma unroll
            for (int mf = 0; mf < 2; mf++)
                LDSM4(af[mf], aB + mf * (16 * 80) + ks * 32);
            uint32_t bfm[4][4];
#pragma unroll
            for (int np = 0; np < 4; np++)
                LDSM4T(bfm[np], bB + ks * (16 * 272) + np * 32);
#pragma unroll
            for (int np = 0; np < 4; np++)
#pragma unroll
                for (int hh = 0; hh < 2; hh++) {
                    int nf = np * 2 + hh;
#pragma unroll
                    for (int mf = 0; mf < 2; mf++)
                        MMA16816(acc[mf][nf], af[mf], bfm[np][hh * 2], bfm[np][hh * 2 + 1]);
                }
        }
        __syncthreads();
    }
#undef ISSUE

    int gid = lane >> 2, tig = lane & 3;
#pragma unroll
    for (int mf = 0; mf < 2; mf++) {
#pragma unroll
        for (int half = 0; half < 2; half++) {
            int r = r0 + wm * 32 + mf * 16 + gid + half * 8;
#pragma unroll
            for (int nf = 0; nf < 8; nf++) {
                int cb = n0 + wn * 64 + nf * 8 + tig * 2;
                float v0 = acc[mf][nf][half * 2 + 0];
                float v1 = acc[mf][nf][half * 2 + 1];
                if (!(flags & FLAG_SPLIT)) {
                    v0 += bias[cb];
                    v1 += bias[cb + 1];
                    if (flags & FLAG_RELU) { v0 = fmaxf(v0, 0.f); v1 = fmaxf(v1, 0.f); }
                }
                if (flags & FLAG_HALFOUT) {
                    *(__half2*)&Ch[(size_t)r * N + cb] = __floats2half2_rn(v0, v1);
                } else {
                    Cout[(size_t)r * N + cb]     = v0;
                    Cout[(size_t)r * N + cb + 1] = v1;
                }
            }
        }
    }
}

// ---------------- gathered edge GEMM chunk: compact rows [rowStart[lo], rowStart[hi]) ----
__global__ __launch_bounds__(512)
void gemm_gather(const float* __restrict__ A, const __half* __restrict__ W16,
                 const float* __restrict__ bias, __half* __restrict__ C,
                 int rowLo, int rowHi) {
    __shared__ __align__(16) __half A_sh[2][128][40];    // 20.0 KB
    __shared__ __align__(16) __half B_sh[2][32][264];    // 33.0 KB
    __shared__ int src[128];

    int tid = threadIdx.x;
    int start = g_rowStart[rowLo];
    int end   = g_rowStart[rowHi];
    int r0 = start + blockIdx.x * 128;
    if (r0 >= end) return;
    if (tid < 128) {
        int gidx = r0 + tid;
        src[tid] = g_rowIdx[gidx < end ? gidx : end - 1];
    }
    __syncthreads();
    const int K = D_, N = D_;

    int aR = tid >> 2, aC = tid & 3;
    const float* aPtr = A + (size_t)src[aR] * K + aC * 8;
    int bR = tid >> 5, bC = tid & 31;
    const __half* bS1 = W16 + (size_t)bR * N + bC * 8;
    const __half* bS2 = W16 + (size_t)(bR + 16) * N + bC * 8;
    uint32_t bD1 = smemAddr(&B_sh[0][bR][bC * 8]);
    uint32_t bD2 = smemAddr(&B_sh[0][bR + 16][bC * 8]);
    const int A_BUF = 128 * 40 * 2;
    const int B_BUF = 32 * 264 * 2;

    uint32_t pa[4];
#define LOADA(off)                                                               \
    do {                                                                         \
        float4 t0 = *(const float4*)(aPtr + (off));                              \
        float4 t1 = *(const float4*)(aPtr + (off) + 4);                          \
        pa[0] = packh2(t0.x, t0.y); pa[1] = packh2(t0.z, t0.w);                  \
        pa[2] = packh2(t1.x, t1.y); pa[3] = packh2(t1.z, t1.w);                  \
    } while (0)
#define STOREA(BF) \
    *(uint4*)&A_sh[BF][aR][aC * 8] = make_uint4(pa[0], pa[1], pa[2], pa[3])
#define ISSUEB(st, koff)                                                         \
    do {                                                                         \
        CP16(bD1 + (st) * B_BUF, bS1 + (size_t)(koff) * N);                      \
        CP16(bD2 + (st) * B_BUF, bS2 + (size_t)(koff) * N);                      \
    } while (0)

    float acc[2][8][4];
#pragma unroll
    for (int i = 0; i < 2; i++)
#pragma unroll
        for (int j = 0; j < 8; j++)
#pragma unroll
            for (int l = 0; l < 4; l++) acc[i][j][l] = 0.0f;

    int wid = tid >> 5, lane = tid & 31;
    int wm = wid & 3, wn = wid >> 2;
    int lrow = lane & 15, lcol = lane >> 4;
    uint32_t aLd = smemAddr(&A_sh[0][wm * 32 + lrow][lcol * 8]);
    uint32_t bLd = smemAddr(&B_sh[0][lrow][wn * 64 + lcol * 8]);

    LOADA(0);
    ISSUEB(0, 0);
    CPCOMMIT();
    STOREA(0);
    CPWAIT0();
    __syncthreads();

    int buf = 0;
#pragma unroll 1
    for (int it = 0; it < 8; it++) {
        if (it + 1 < 8) {
            LOADA((it + 1) * 32);
            ISSUEB(buf ^ 1, (it + 1) * 32);
        }
        CPCOMMIT();
        uint32_t aB = aLd + buf * A_BUF;
        uint32_t bB = bLd + buf * B_BUF;
#pragma unroll
        for (int ks = 0; ks < 2; ks++) {
            uint32_t af[2][4];
#pragma unroll
            for (int mf = 0; mf < 2; mf++)
                LDSM4(af[mf], aB + mf * (16 * 80) + ks * 32);
            uint32_t bfm[4][4];
#pragma unroll
            for (int np = 0; np < 4; np++)
                LDSM4T(bfm[np], bB + ks * (16 * 528) + np * 32);
#pragma unroll
            for (int np = 0; np < 4; np++)
#pragma unroll
                for (int hh = 0; hh < 2; hh++) {
                    int nf = np * 2 + hh;
#pragma unroll
                    for (int mf = 0; mf < 2; mf++)
                        MMA16816(acc[mf][nf], af[mf], bfm[np][hh * 2], bfm[np][hh * 2 + 1]);
                }
        }
        if (it + 1 < 8) STOREA(buf ^ 1);
        CPWAIT0();
        __syncthreads();
        buf ^= 1;
    }
#undef LOADA
#undef STOREA
#undef ISSUEB

    int gid = lane >> 2, tig = lane & 3;
#pragma unroll
    for (int mf = 0; mf < 2; mf++) {
#pragma unroll
        for (int half = 0; half < 2; half++) {
            int r = r0 + wm * 32 + mf * 16 + gid + half * 8;
            bool rok = r < end;
#pragma unroll
            for (int nf = 0; nf < 8; nf++) {
                int cb = wn * 64 + nf * 8 + tig * 2;
                if (rok) {
                    float v0 = acc[mf][nf][half * 2 + 0] + bias[cb];
                    float v1 = acc[mf][nf][half * 2 + 1] + bias[cb + 1];
                    *(__half2*)&C[(size_t)r * N + cb] = __floats2half2_rn(v0, v1);
                }
            }
        }
    }
}

// ---------------- split-K reduction for FFN-2 (+bias +residual) -> out ----------------
__global__ void f2red_kernel(const float* __restrict__ bias, float* __restrict__ out) {
    int i = blockIdx.x * 256 + threadIdx.x;
    int c = i & 255;
    out[i] = g_me2[i] + bias[c]
           + g_f2part[i] + g_f2part[65536 + i]
           + g_f2part[131072 + i] + g_f2part[196608 + i];
}

// ---------------- attention: online softmax single pass (+ proj + resid + LN2) ------
__global__ __launch_bounds__(256)
void attn_kernel(const float* __restrict__ machine_emb,
                 const float* __restrict__ Wo, const float* __restrict__ bo,
                 const float* __restrict__ g2, const float* __restrict__ bn2,
                 int rowBase) {
    __shared__ float ao[D_];
    __shared__ int   sn[N_];
    __shared__ float red[16];
    int row = rowBase + blockIdx.x;
    int b = row >> 6;
    int tid = threadIdx.x, lane = tid & 31, h = tid >> 5;
    int cnt = g_actCnt[row];
    int start = g_rowStart[row];

    for (int i = tid; i < cnt; i += 256) sn[i] = g_actN[row * N_ + i];
    __syncthreads();

    int g = lane >> 3, d8 = lane & 7;
    const float* qkvRow = g_qkv + (size_t)row * 768;
    float4 q4  = ((const float4*)(qkvRow +       h * 32))[d8];
    float4 ks4 = ((const float4*)(qkvRow + 256 + h * 32))[d8];
    float4 vs4 = ((const float4*)(qkvRow + 512 + h * 32))[d8];

    float sSelf = q4.x * ks4.x + q4.y * ks4.y + q4.z * ks4.z + q4.w * ks4.w;
#pragma unroll
    for (int o = 1; o < 8; o <<= 1) sSelf += __shfl_xor_sync(0xffffffffu, sSelf, o);
    sSelf *= SCALE_;

    const __half* Eb = g_Eh  + (size_t)start * D_ + h * 32 + d8 * 4;
    const __half* Kb = g_kvh + (size_t)b * N_ * 512 + h * 32 + d8 * 4;
    const __half* Vb = Kb + 256;

    float mx = (g == 0) ? sSelf : BIG_NEG;
    float sm = (g == 0) ? 1.0f : 0.0f;
    float4 acc = make_float4(0.f, 0.f, 0.f, 0.f);
    if (g == 0) { acc.x = vs4.x; acc.y = vs4.y; acc.z = vs4.z; acc.w = vs4.w; }

#pragma unroll 2
    for (int j0 = 0; j0 < cnt; j0 += 4) {
        int j = j0 + g;
        bool ok = j < cnt;
        float t = 0.0f;
        float2 e01, e23, v01, v23;
        if (ok) {
            int n = sn[j];
            uint2 eu = *(const uint2*)(Eb + (size_t)j * D_);
            uint2 ku = *(const uint2*)(Kb + (size_t)n * 512);
            uint2 vu = *(const uint2*)(Vb + (size_t)n * 512);
            e01 = __half22float2(*(__half2*)&eu.x);
            e23 = __half22float2(*(__half2*)&eu.y);
            float2 k01 = __half22float2(*(__half2*)&ku.x);
            float2 k23 = __half22float2(*(__half2*)&ku.y);
            v01 = __half22float2(*(__half2*)&vu.x);
            v23 = __half22float2(*(__half2*)&vu.y);
            t = (q4.x + e01.x) * (k01.x + e01.x) + (q4.y + e01.y) * (k01.y + e01.y)
              + (q4.z + e23.x) * (k23.x + e23.x) + (q4.w + e23.y) * (k23.y + e23.y);
        }
#pragma unroll
        for (int o = 1; o < 8; o <<= 1) t += __shfl_xor_sync(0xffffffffu, t, o);
        if (ok) {
            t *= SCALE_;
            float nm = fmaxf(mx, t);
            float sc = __expf(mx - nm);
            float p  = __expf(t - nm);
            mx = nm;
            sm = sm * sc + p;
            acc.x = fmaf(acc.x, sc, p * (v01.x + e01.x));
            acc.y = fmaf(acc.y, sc, p * (v01.y + e01.y));
            acc.z = fmaf(acc.z, sc, p * (v23.x + e23.x));
            acc.w = fmaf(acc.w, sc, p * (v23.y + e23.y));
        }
    }

#pragma unroll
    for (int o = 8; o < 32; o <<= 1) {
        float pmx = __shfl_xor_sync(0xffffffffu, mx, o);
        float psm = __shfl_xor_sync(0xffffffffu, sm, o);
        float pax = __shfl_xor_sync(0xffffffffu, acc.x, o);
        float pay = __shfl_xor_sync(0xffffffffu, acc.y, o);
        float paz = __shfl_xor_sync(0xffffffffu, acc.z, o);
        float paw = __shfl_xor_sync(0xffffffffu, acc.w, o);
        float nm = fmaxf(mx, pmx);
        float s1 = __expf(mx - nm);
        float s2 = __expf(pmx - nm);
        mx = nm;
        sm = sm * s1 + psm * s2;
        acc.x = acc.x * s1 + pax * s2;
        acc.y = acc.y * s1 + pay * s2;
        acc.z = acc.z * s1 + paz * s2;
        acc.w = acc.w * s1 + paw * s2;
    }
    if (g == 0) {
        float inv = 1.0f / sm;
        float4 r = make_float4(acc.x * inv, acc.y * inv, acc.z * inv, acc.w * inv);
        *(float4*)(ao + h * 32 + d8 * 4) = r;
    }
    __syncthreads();

    float r = machine_emb[(size_t)row * D_ + tid] + bo[tid];
#pragma unroll 8
    for (int k = 0; k < D_; k++) r = fmaf(ao[k], Wo[(size_t)k * D_ + tid], r);
    g_me2[(size_t)row * D_ + tid] = r;

    float s  = warpSum(r);
    float s2 = warpSum(r * r);
    if ((tid & 31) == 0) { red[tid >> 5] = s; red[8 + (tid >> 5)] = s2; }
    __syncthreads();
    float sum = 0.f, sum2 = 0.f;
#pragma unroll
    for (int i = 0; i < 8; i++) { sum += red[i]; sum2 += red[8 + i]; }
    float mu  = sum * (1.0f / D_);
    float var = sum2 * (1.0f / D_) - mu * mu;
    float invs = rsqrtf(var + EPS_);
    g_h16[(size_t)row * D_ + tid] = __float2half((r - mu) * invs * g2[tid] + bn2[tid]);
}

// ---------------- launch ----------------
template <typename T>
static T* symAddr(const void* sym) {
    void* p = nullptr;
    cudaGetSymbolAddress(&p, sym);
    return (T*)p;
}

extern "C" void kernel_launch(void* const* d_in, const int* in_sizes, int n_in,
                              void* d_out, int out_size) {
    const float* machine_emb = (const float*)d_in[0];
    const float* op_emb      = (const float*)d_in[1];
    const float* edge_emb    = (const float*)d_in[2];
    const void*  mask        = d_in[3];
    const float* Wq  = (const float*)d_in[4];
    const float* bq  = (const float*)d_in[5];
    const float* Wk  = (const float*)d_in[6];
    const float* bk  = (const float*)d_in[7];
    const float* Wv  = (const float*)d_in[8];
    const float* bv  = (const float*)d_in[9];
    const float* Wo  = (const float*)d_in[10];
    const float* bo  = (const float*)d_in[11];
    const float* Wks = (const float*)d_in[12];
    const float* bks = (const float*)d_in[13];
    const float* Wvs = (const float*)d_in[14];
    const float* bvs = (const float*)d_in[15];
    const float* We  = (const float*)d_in[16];
    const float* be  = (const float*)d_in[17];
    const float* g1  = (const float*)d_in[18];
    const float* bn1 = (const float*)d_in[19];
    const float* g2  = (const float*)d_in[20];
    const float* bn2 = (const float*)d_in[21];
    const float* gop = (const float*)d_in[22];
    const float* bnop= (const float*)d_in[23];
    const float* Wf1 = (const float*)d_in[24];
    const float* bf1 = (const float*)d_in[25];
    const float* Wf2 = (const float*)d_in[26];
    const float* bf2 = (const float*)d_in[27];
    float* out = (float*)d_out;

    __half* p_mnorm16 = symAddr<__half>(g_mnorm16);
    __half* p_onorm16 = symAddr<__half>(g_onorm16);
    __half* p_Wqkv16  = symAddr<__half>(g_Wqkv16);
    __half* p_Wkv16   = symAddr<__half>(g_Wkv16);
    __half* p_We16    = symAddr<__half>(g_We16);
    __half* p_Wf1_16  = symAddr<__half>(g_Wf1_16);
    __half* p_Wf2_16  = symAddr<__half>(g_Wf2_16);
    __half* p_f1h     = symAddr<__half>(g_f1h);
    __half* p_h16     = symAddr<__half>(g_h16);
    __half* p_kvh     = symAddr<__half>(g_kvh);
    __half* p_Eh      = symAddr<__half>(g_Eh);
    float* p_bqkv = symAddr<float>(g_bqkv);
    float* p_bkv  = symAddr<float>(g_bkv);
    float* p_qkv  = symAddr<float>(g_qkv);
    float* p_f2p  = symAddr<float>(g_f2part);

    static cudaStream_t s1 = nullptr, s2 = nullptr;
    static cudaEvent_t eFork = nullptr, ePack = nullptr;
    static cudaEvent_t eG[4] = {nullptr, nullptr, nullptr, nullptr};
    static cudaEvent_t eA = nullptr;
    if (!s1) {
        cudaStreamCreateWithFlags(&s1, cudaStreamNonBlocking);
        cudaStreamCreateWithFlags(&s2, cudaStreamNonBlocking);
        cudaEventCreateWithFlags(&eFork, cudaEventDisableTiming);
        cudaEventCreateWithFlags(&ePack, cudaEventDisableTiming);
        for (int q = 0; q < 4; q++)
            cudaEventCreateWithFlags(&eG[q], cudaEventDisableTiming);
        cudaEventCreateWithFlags(&eA, cudaEventDisableTiming);
    }

    // ---- fork ----
    cudaEventRecord(eFork, 0);
    cudaStreamWaitEvent(s1, eFork, 0);
    cudaStreamWaitEvent(s2, eFork, 0);

    // branch s2: weight packing (fp16)
    pack_kernel<<<320, 1024, 0, s2>>>(Wq, bq, Wks, bks, Wvs, bvs, Wk, bk, Wv, bv,
                                      Wf1, Wf2, We);
    cudaEventRecord(ePack, s2);

    // branch s1: layernorms -> fused projections -> (chunked attention, below)
    ln_kernel<<<ROWS_M, 256, 0, s1>>>(machine_emb, g1, bn1, p_mnorm16);
    ln_kernel<<<ROWS_O, 256, 0, s1>>>(op_emb, gop, bnop, p_onorm16);
    cudaStreamWaitEvent(s1, ePack, 0);
    {
        dim3 gQ(ROWS_M / 128, 768 / 128);
        gemm_h<<<gQ, 256, 0, s1>>>(p_mnorm16, p_Wqkv16, p_bqkv, p_qkv, nullptr,
                                   D_, 768, D_, 0, 0);
        dim3 gKV(ROWS_O / 128, 512 / 128);
        gemm_h<<<gKV, 256, 0, s1>>>(p_onorm16, p_Wkv16, p_bkv, nullptr, p_kvh,
                                    D_, 512, D_, 0, FLAG_HALFOUT);
    }

    // main branch: compaction chain -> 4 gather chunks (row-space aligned)
    detect_kernel<<<256, 256>>>((const unsigned char*)mask, in_sizes[3]);
    actlist_kernel<<<32, 256>>>(mask);
    prefixfill_kernel<<<ROWS_M, 256>>>();
    cudaStreamWaitEvent(0, ePack, 0);   // gather needs fp16 We
    for (int q = 0; q < 4; q++) {
        gemm_gather<<<256, 512>>>(edge_emb, p_We16, be, p_Eh, q * 64, q * 64 + 64);
        cudaEventRecord(eG[q], 0);
    }

    // chunked attention on s1, pipelined behind gather chunks
    for (int q = 0; q < 4; q++) {
        cudaStreamWaitEvent(s1, eG[q], 0);
        attn_kernel<<<64, 256, 0, s1>>>(machine_emb, Wo, bo, g2, bn2, q * 64);
    }
    cudaEventRecord(eA, s1);

    // FFN (R10 3-launch form) after all attention chunks
    cudaStreamWaitEvent(0, eA, 0);
    {
        dim3 gF1(ROWS_M / 128, F_ / 128);
        gemm_h<<<gF1, 256>>>(p_h16, p_Wf1_16, bf1, nullptr, p_f1h,
                             D_, F_, D_, 0, FLAG_RELU | FLAG_HALFOUT);
        dim3 gF2(ROWS_M / 128, D_ / 128, 4);
        gemm_h<<<gF2, 256>>>(p_f1h, p_Wf2_16, bf2, p_f2p, nullptr,
                             F_, D_, F_ / 4, ROWS_M * D_, FLAG_SPLIT);
    }
    f2red_kernel<<<ROWS_M, 256>>>(bf2, out);
}

// round 13
// speedup vs baseline: 1.5668x; 1.5668x over previous
#include <cuda_runtime.h>
#include <cuda_fp16.h>
#include <cstdint>

// ---------------- problem constants ----------------
#define D_      256
#define B_      4
#define M_      64
#define N_      512
#define H_      8
#define F_      1024
#define ROWS_M  256        // B*M
#define ROWS_O  2048       // B*N
#define NEDGE   131072     // B*N*M
#define SCALE_  0.17677669529663687f   // 1/sqrt(32)
#define EPS_    1e-5f
#define BIG_NEG (-1e30f)

#define FLAG_RELU    1
#define FLAG_SPLIT   4
#define FLAG_HALFOUT 8

// ---------------- scratch (device globals; no runtime allocation) ----------------
__device__ __align__(16) __half g_mnorm16[ROWS_M * D_];
__device__ __align__(16) __half g_onorm16[ROWS_O * D_];
__device__ __align__(16) __half g_Wqkv16[D_ * 768];
__device__ __align__(16) __half g_Wkv16 [D_ * 512];
__device__ __align__(16) __half g_We16  [D_ * D_];
__device__ __align__(16) __half g_Wf1_16[D_ * F_];
__device__ __align__(16) __half g_Wf2_16[F_ * D_];
__device__ __align__(16) __half g_f1h   [ROWS_M * F_];
__device__ __align__(16) __half g_h16   [ROWS_M * D_];
__device__ __align__(16) __half g_kvh   [ROWS_O * 512];      // 0:256 k | 256:512 v (fp16)
__device__ __align__(16) __half g_Eh    [(size_t)NEDGE * D_];// compacted projected edges fp16
__device__ float g_bqkv[768];
__device__ float g_bkv [512];
__device__ float g_qkv [ROWS_M * 768];        // 0:256 q | 256:512 ks | 512:768 vs
__device__ float g_me2 [ROWS_M * D_];
__device__ float g_f2part[4 * ROWS_M * D_];
__device__ int   g_actN[ROWS_M * N_];
__device__ int   g_actCnt[ROWS_M];
__device__ int   g_rowStart[ROWS_M + 1];
__device__ int   g_rowIdx[NEDGE];
__device__ int   g_count;
__device__ int   g_flagGt1, g_flagNz;

// ---------------- helpers ----------------
__device__ __forceinline__ float warpSum(float v) {
#pragma unroll
    for (int o = 16; o; o >>= 1) v += __shfl_xor_sync(0xffffffffu, v, o);
    return v;
}
__device__ __forceinline__ uint32_t packh2(float x, float y) {
    __half2 h = __floats2half2_rn(x, y);
    return *reinterpret_cast<uint32_t*>(&h);
}
__device__ __forceinline__ uint32_t smemAddr(const void* p) {
    return (uint32_t)__cvta_generic_to_shared(p);
}

#define CP16(d, s) asm volatile("cp.async.ca.shared.global [%0], [%1], 16;" :: "r"(d), "l"(s))
#define CPCOMMIT() asm volatile("cp.async.commit_group;")
#define CPWAIT0()  asm volatile("cp.async.wait_group 0;")
#define CPWAIT1()  asm volatile("cp.async.wait_group 1;")

#define LDSM4(r, addr)                                                          \
    asm volatile("ldmatrix.sync.aligned.m8n8.x4.shared.b16 {%0,%1,%2,%3}, [%4];"\
                 : "=r"((r)[0]), "=r"((r)[1]), "=r"((r)[2]), "=r"((r)[3])       \
                 : "r"(addr))
#define LDSM4T(r, addr)                                                         \
    asm volatile("ldmatrix.sync.aligned.m8n8.x4.trans.shared.b16 {%0,%1,%2,%3}, [%4];" \
                 : "=r"((r)[0]), "=r"((r)[1]), "=r"((r)[2]), "=r"((r)[3])       \
                 : "r"(addr))
#define MMA16816(d, a, b0v, b1v)                                                \
    asm volatile("mma.sync.aligned.m16n8k16.row.col.f32.f16.f16.f32 "           \
                 "{%0,%1,%2,%3},{%4,%5,%6,%7},{%8,%9},{%0,%1,%2,%3};"           \
                 : "+f"((d)[0]), "+f"((d)[1]), "+f"((d)[2]), "+f"((d)[3])       \
                 : "r"((a)[0]), "r"((a)[1]), "r"((a)[2]), "r"((a)[3]),          \
                   "r"(b0v), "r"(b1v))

// ---------------- mask preprocessing ----------------
__global__ void detect_kernel(const unsigned char* __restrict__ p, int nbytes) {
    int i = blockIdx.x * blockDim.x + threadIdx.x;
    int stride = gridDim.x * blockDim.x;
    int gt1 = 0, nz = 0;
    for (; i < nbytes; i += stride) {
        unsigned char v = p[i];
        gt1 |= (v > 1);
        nz  |= (v != 0 && (i & 3) != 0);
    }
    if (__any_sync(0xffffffffu, gt1) && (threadIdx.x & 31) == 0) atomicOr(&g_flagGt1, 1);
    if (__any_sync(0xffffffffu, nz)  && (threadIdx.x & 31) == 0) atomicOr(&g_flagNz, 1);
}

__global__ void actlist_kernel(const void* __restrict__ mask) {
    int wid = threadIdx.x >> 5, lane = threadIdx.x & 31;
    int row = blockIdx.x * 8 + wid;
    int b = row >> 6, m = row & 63;
    int mode = g_flagGt1 ? 2 : (g_flagNz ? 1 : 0);
    int base = 0;
#pragma unroll 1
    for (int c = 0; c < 16; c++) {
        int n = c * 32 + lane;
        size_t mi = ((size_t)(b * N_ + n)) * M_ + m;
        bool a;
        if (mode == 2)      a = ((const float*)mask)[mi] != 0.0f;
        else if (mode == 1) a = ((const unsigned char*)mask)[mi] != 0;
        else                a = ((const int*)mask)[mi] != 0;
        unsigned bal = __ballot_sync(0xffffffffu, a);
        if (a) g_actN[row * N_ + base + __popc(bal & ((1u << lane) - 1u))] = n;
        base += __popc(bal);
    }
    if (lane == 0) g_actCnt[row] = base;
}

// Merged prefix + fill; resets mask flags for next replay.
__global__ void prefixfill_kernel() {
    __shared__ int ws[8];
    __shared__ int startS;
    int tid = threadIdx.x;
    int row = blockIdx.x;
    int v = g_actCnt[tid];
    int lane = tid & 31, w = tid >> 5;
    int inc = v;
#pragma unroll
    for (int o = 1; o < 32; o <<= 1) {
        int t = __shfl_up_sync(0xffffffffu, inc, o);
        if (lane >= o) inc += t;
    }
    if (lane == 31) ws[w] = inc;
    __syncthreads();
    int add = 0;
#pragma unroll
    for (int i = 0; i < 8; i++) if (i < w) add += ws[i];
    int excl = inc - v + add;
    if (row == 0) {
        g_rowStart[tid] = excl;
        if (tid == 255) { g_rowStart[256] = excl + v; g_count = excl + v; }
        if (tid == 0) { g_flagGt1 = 0; g_flagNz = 0; }
    }
    if (tid == row) startS = excl;
    __syncthreads();
    int myStart = startS;
    int myCnt = g_actCnt[row];
    int b = row >> 6, m = row & 63;
    for (int i = tid; i < myCnt; i += 256) {
        int n = g_actN[row * N_ + i];
        g_rowIdx[myStart + i] = (b * N_ + n) * M_ + m;
    }
}

// ---------------- weight packing -> fp16 ----------------
// We packed FIRST (tiny) so the gather GEMM can start early.
__global__ void pack_we_kernel(const float* __restrict__ We) {
    int i = blockIdx.x * 1024 + threadIdx.x;   // grid 64 x 1024 == 65536 elems
    g_We16[i] = __float2half(We[i]);
}

__global__ void pack_kernel(const float* __restrict__ Wq,  const float* __restrict__ bq,
                            const float* __restrict__ Wks, const float* __restrict__ bks,
                            const float* __restrict__ Wvs, const float* __restrict__ bvs,
                            const float* __restrict__ Wk,  const float* __restrict__ bk,
                            const float* __restrict__ Wv,  const float* __restrict__ bv,
                            const float* __restrict__ Wf1, const float* __restrict__ Wf2) {
    int stride = gridDim.x * blockDim.x;
    int i0 = blockIdx.x * blockDim.x + threadIdx.x;
    for (int i = i0; i < D_ * 768; i += stride) {
        int k = i / 768, c = i % 768;
        float v = (c < 256) ? Wq[k * 256 + c]
                : (c < 512) ? Wks[k * 256 + c - 256]
                            : Wvs[k * 256 + c - 512];
        g_Wqkv16[i] = __float2half(v);
    }
    for (int i = i0; i < D_ * 512; i += stride) {
        int k = i / 512, c = i % 512;
        g_Wkv16[i] = __float2half((c < 256) ? Wk[k * 256 + c] : Wv[k * 256 + c - 256]);
    }
    for (int i = i0; i < D_ * F_; i += stride) g_Wf1_16[i] = __float2half(Wf1[i]);
    for (int i = i0; i < F_ * D_; i += stride) g_Wf2_16[i] = __float2half(Wf2[i]);
    if (i0 < 768)
        g_bqkv[i0] = (i0 < 256) ? bq[i0] : (i0 < 512) ? bks[i0 - 256] : bvs[i0 - 512];
    if (i0 < 512)
        g_bkv[i0] = (i0 < 256) ? bk[i0] : bv[i0 - 256];
}

// ---------------- layernorm (fp32 in -> fp16 out) ----------------
__global__ void ln_kernel(const float* __restrict__ x, const float* __restrict__ g,
                          const float* __restrict__ beta, __half* __restrict__ y) {
    __shared__ float red[16];
    int row = blockIdx.x;
    int tid = threadIdx.x;
    float v = x[(size_t)row * D_ + tid];
    float s  = warpSum(v);
    float s2 = warpSum(v * v);
    if ((tid & 31) == 0) { red[tid >> 5] = s; red[8 + (tid >> 5)] = s2; }
    __syncthreads();
    float sum = 0.f, sum2 = 0.f;
#pragma unroll
    for (int i = 0; i < 8; i++) { sum += red[i]; sum2 += red[8 + i]; }
    float mu  = sum * (1.0f / D_);
    float var = sum2 * (1.0f / D_) - mu * mu;
    float inv = rsqrtf(var + EPS_);
    y[(size_t)row * D_ + tid] = __float2half((v - mu) * inv * g[tid] + beta[tid]);
}

// ---------------- fp16/fp16 GEMM, cp.async 3-stage: 128x128 tile, 8 warps ----------
__global__ __launch_bounds__(256)
void gemm_h(const __half* __restrict__ A, const __half* __restrict__ W,
            const float* __restrict__ bias, float* __restrict__ C,
            __half* __restrict__ Ch,
            int K, int N, int kChunk, int partStride, int flags) {
    __shared__ __align__(16) __half A_sh[3][128][40];
    __shared__ __align__(16) __half B_sh[3][32][136];

    int tid = threadIdx.x;
    int r0 = blockIdx.x * 128, n0 = blockIdx.y * 128;
    int kb0 = blockIdx.z * kChunk;
    float* Cout = C + (size_t)blockIdx.z * partStride;

    int a1 = tid, a2 = tid + 256;
    int aR1 = a1 >> 2, aC1 = a1 & 3, aR2 = a2 >> 2, aC2 = a2 & 3;
    const __half* aS1 = A + (size_t)(r0 + aR1) * K + kb0 + aC1 * 8;
    const __half* aS2 = A + (size_t)(r0 + aR2) * K + kb0 + aC2 * 8;
    uint32_t aD1 = smemAddr(&A_sh[0][aR1][aC1 * 8]);
    uint32_t aD2 = smemAddr(&A_sh[0][aR2][aC2 * 8]);
    int bR1 = tid >> 4, bC = tid & 15, bR2 = bR1 + 16;
    const __half* bS1 = W + (size_t)(kb0 + bR1) * N + n0 + bC * 8;
    const __half* bS2 = W + (size_t)(kb0 + bR2) * N + n0 + bC * 8;
    uint32_t bD1 = smemAddr(&B_sh[0][bR1][bC * 8]);
    uint32_t bD2 = smemAddr(&B_sh[0][bR2][bC * 8]);
    const int ABUF = 128 * 40 * 2, BBUF = 32 * 136 * 2;

#define ISSUE(st, koff)                                                         \
    do {                                                                        \
        CP16(aD1 + (st) * ABUF, aS1 + (koff));                                  \
        CP16(aD2 + (st) * ABUF, aS2 + (koff));                                  \
        CP16(bD1 + (st) * BBUF, bS1 + (size_t)(koff) * N);                      \
        CP16(bD2 + (st) * BBUF, bS2 + (size_t)(koff) * N);                      \
    } while (0)

    float acc[2][8][4];
#pragma unroll
    for (int i = 0; i < 2; i++)
#pragma unroll
        for (int j = 0; j < 8; j++)
#pragma unroll
            for (int l = 0; l < 4; l++) acc[i][j][l] = 0.0f;

    int wid = tid >> 5, lane = tid & 31;
    int wm = wid & 3, wn = wid >> 2;
    int lrow = lane & 15, lcol = lane >> 4;
    uint32_t aLd = smemAddr(&A_sh[0][wm * 32 + lrow][lcol * 8]);
    uint32_t bLd = smemAddr(&B_sh[0][lrow][wn * 64 + lcol * 8]);

    int nIter = kChunk / 32;
    ISSUE(0, 0);
    CPCOMMIT();
    if (nIter > 1) ISSUE(1, 32);
    CPCOMMIT();

#pragma unroll 1
    for (int it = 0; it < nIter; it++) {
        CPWAIT1();
        __syncthreads();
        int st = it % 3;
        int nx = it + 2;
        if (nx < nIter) ISSUE(nx % 3, nx * 32);
        CPCOMMIT();
        uint32_t aB = aLd + st * ABUF;
        uint32_t bB = bLd + st * BBUF;
#pragma unroll
        for (int ks = 0; ks < 2; ks++) {
            uint32_t af[2][4];
#pragma unroll
            for (int mf = 0; mf < 2; mf++)
                LDSM4(af[mf], aB + mf * (16 * 80) + ks * 32);
            uint32_t bfm[4][4];
#pragma unroll
            for (int np = 0; np < 4; np++)
                LDSM4T(bfm[np], bB + ks * (16 * 272) + np * 32);
#pragma unroll
            for (int np = 0; np < 4; np++)
#pragma unroll
                for (int hh = 0; hh < 2; hh++) {
                    int nf = np * 2 + hh;
#pragma unroll
                    for (int mf = 0; mf < 2; mf++)
                        MMA16816(acc[mf][nf], af[mf], bfm[np][hh * 2], bfm[np][hh * 2 + 1]);
                }
        }
        __syncthreads();
    }
#undef ISSUE

    int gid = lane >> 2, tig = lane & 3;
#pragma unroll
    for (int mf = 0; mf < 2; mf++) {
#pragma unroll
        for (int half = 0; half < 2; half++) {
            int r = r0 + wm * 32 + mf * 16 + gid + half * 8;
#pragma unroll
            for (int nf = 0; nf < 8; nf++) {
                int cb = n0 + wn * 64 + nf * 8 + tig * 2;
                float v0 = acc[mf][nf][half * 2 + 0];
                float v1 = acc[mf][nf][half * 2 + 1];
                if (!(flags & FLAG_SPLIT)) {
                    v0 += bias[cb];
                    v1 += bias[cb + 1];
                    if (flags & FLAG_RELU) { v0 = fmaxf(v0, 0.f); v1 = fmaxf(v1, 0.f); }
                }
                if (flags & FLAG_HALFOUT) {
                    *(__half2*)&Ch[(size_t)r * N + cb] = __floats2half2_rn(v0, v1);
                } else {
                    Cout[(size_t)r * N + cb]     = v0;
                    Cout[(size_t)r * N + cb + 1] = v1;
                }
            }
        }
    }
}

// ---------------- gathered edge GEMM: 128x256 tile, 512 threads (16 warps) ----------
__global__ __launch_bounds__(512)
void gemm_gather(const float* __restrict__ A, const __half* __restrict__ W16,
                 const float* __restrict__ bias, __half* __restrict__ C) {
    __shared__ __align__(16) __half A_sh[2][128][40];    // 20.0 KB
    __shared__ __align__(16) __half B_sh[2][32][264];    // 33.0 KB
    __shared__ int src[128];

    int tid = threadIdx.x;
    int count = g_count;
    int r0 = blockIdx.x * 128;
    if (r0 >= count) return;
    if (tid < 128) {
        int gidx = r0 + tid;
        src[tid] = g_rowIdx[gidx < count ? gidx : count - 1];
    }
    __syncthreads();
    const int K = D_, N = D_;

    int aR = tid >> 2, aC = tid & 3;
    const float* aPtr = A + (size_t)src[aR] * K + aC * 8;
    int bR = tid >> 5, bC = tid & 31;
    const __half* bS1 = W16 + (size_t)bR * N + bC * 8;
    const __half* bS2 = W16 + (size_t)(bR + 16) * N + bC * 8;
    uint32_t bD1 = smemAddr(&B_sh[0][bR][bC * 8]);
    uint32_t bD2 = smemAddr(&B_sh[0][bR + 16][bC * 8]);
    const int A_BUF = 128 * 40 * 2;
    const int B_BUF = 32 * 264 * 2;

    uint32_t pa[4];
#define LOADA(off)                                                               \
    do {                                                                         \
        float4 t0 = *(const float4*)(aPtr + (off));                              \
        float4 t1 = *(const float4*)(aPtr + (off) + 4);                          \
        pa[0] = packh2(t0.x, t0.y); pa[1] = packh2(t0.z, t0.w);                  \
        pa[2] = packh2(t1.x, t1.y); pa[3] = packh2(t1.z, t1.w);                  \
    } while (0)
#define STOREA(BF) \
    *(uint4*)&A_sh[BF][aR][aC * 8] = make_uint4(pa[0], pa[1], pa[2], pa[3])
#define ISSUEB(st, koff)                                                         \
    do {                                                                         \
        CP16(bD1 + (st) * B_BUF, bS1 + (size_t)(koff) * N);                      \
        CP16(bD2 + (st) * B_BUF, bS2 + (size_t)(koff) * N);                      \
    } while (0)

    float acc[2][8][4];
#pragma unroll
    for (int i = 0; i < 2; i++)
#pragma unroll
        for (int j = 0; j < 8; j++)
#pragma unroll
            for (int l = 0; l < 4; l++) acc[i][j][l] = 0.0f;

    int wid = tid >> 5, lane = tid & 31;
    int wm = wid & 3, wn = wid >> 2;
    int lrow = lane & 15, lcol = lane >> 4;
    uint32_t aLd = smemAddr(&A_sh[0][wm * 32 + lrow][lcol * 8]);
    uint32_t bLd = smemAddr(&B_sh[0][lrow][wn * 64 + lcol * 8]);

    LOADA(0);
    ISSUEB(0, 0);
    CPCOMMIT();
    STOREA(0);
    CPWAIT0();
    __syncthreads();

    int buf = 0;
#pragma unroll 1
    for (int it = 0; it < 8; it++) {
        if (it + 1 < 8) {
            LOADA((it + 1) * 32);
            ISSUEB(buf ^ 1, (it + 1) * 32);
        }
        CPCOMMIT();
        uint32_t aB = aLd + buf * A_BUF;
        uint32_t bB = bLd + buf * B_BUF;
#pragma unroll
        for (int ks = 0; ks < 2; ks++) {
            uint32_t af[2][4];
#pragma unroll
            for (int mf = 0; mf < 2; mf++)
                LDSM4(af[mf], aB + mf * (16 * 80) + ks * 32);
            uint32_t bfm[4][4];
#pragma unroll
            for (int np = 0; np < 4; np++)
                LDSM4T(bfm[np], bB + ks * (16 * 528) + np * 32);
#pragma unroll
            for (int np = 0; np < 4; np++)
#pragma unroll
                for (int hh = 0; hh < 2; hh++) {
                    int nf = np * 2 + hh;
#pragma unroll
                    for (int mf = 0; mf < 2; mf++)
                        MMA16816(acc[mf][nf], af[mf], bfm[np][hh * 2], bfm[np][hh * 2 + 1]);
                }
        }
        if (it + 1 < 8) STOREA(buf ^ 1);
        CPWAIT0();
        __syncthreads();
        buf ^= 1;
    }
#undef LOADA
#undef STOREA
#undef ISSUEB

    int gid = lane >> 2, tig = lane & 3;
#pragma unroll
    for (int mf = 0; mf < 2; mf++) {
#pragma unroll
        for (int half = 0; half < 2; half++) {
            int r = r0 + wm * 32 + mf * 16 + gid + half * 8;
            bool rok = r < count;
#pragma unroll
            for (int nf = 0; nf < 8; nf++) {
                int cb = wn * 64 + nf * 8 + tig * 2;
                if (rok) {
                    float v0 = acc[mf][nf][half * 2 + 0] + bias[cb];
                    float v1 = acc[mf][nf][half * 2 + 1] + bias[cb + 1];
                    *(__half2*)&C[(size_t)r * N + cb] = __floats2half2_rn(v0, v1);
                }
            }
        }
    }
}

// ---------------- split-K reduction for FFN-2 (+bias +residual) -> out ----------------
__global__ void f2red_kernel(const float* __restrict__ bias, float* __restrict__ out) {
    int i = blockIdx.x * 256 + threadIdx.x;
    int c = i & 255;
    out[i] = g_me2[i] + bias[c]
           + g_f2part[i] + g_f2part[65536 + i]
           + g_f2part[131072 + i] + g_f2part[196608 + i];
}

// ---------------- attention: online softmax single pass (+ proj + resid + LN2) ------
__global__ __launch_bounds__(256)
void attn_kernel(const float* __restrict__ machine_emb,
                 const float* __restrict__ Wo, const float* __restrict__ bo,
                 const float* __restrict__ g2, const float* __restrict__ bn2) {
    __shared__ float ao[D_];
    __shared__ int   sn[N_];
    __shared__ float red[16];
    int row = blockIdx.x;
    int b = row >> 6;
    int tid = threadIdx.x, lane = tid & 31, h = tid >> 5;
    int cnt = g_actCnt[row];
    int start = g_rowStart[row];

    for (int i = tid; i < cnt; i += 256) sn[i] = g_actN[row * N_ + i];
    __syncthreads();

    int g = lane >> 3, d8 = lane & 7;
    const float* qkvRow = g_qkv + (size_t)row * 768;
    float4 q4  = ((const float4*)(qkvRow +       h * 32))[d8];
    float4 ks4 = ((const float4*)(qkvRow + 256 + h * 32))[d8];
    float4 vs4 = ((const float4*)(qkvRow + 512 + h * 32))[d8];

    float sSelf = q4.x * ks4.x + q4.y * ks4.y + q4.z * ks4.z + q4.w * ks4.w;
#pragma unroll
    for (int o = 1; o < 8; o <<= 1) sSelf += __shfl_xor_sync(0xffffffffu, sSelf, o);
    sSelf *= SCALE_;

    const __half* Eb = g_Eh  + (size_t)start * D_ + h * 32 + d8 * 4;
    const __half* Kb = g_kvh + (size_t)b * N_ * 512 + h * 32 + d8 * 4;
    const __half* Vb = Kb + 256;

    float mx = (g == 0) ? sSelf : BIG_NEG;
    float sm = (g == 0) ? 1.0f : 0.0f;
    float4 acc = make_float4(0.f, 0.f, 0.f, 0.f);
    if (g == 0) { acc.x = vs4.x; acc.y = vs4.y; acc.z = vs4.z; acc.w = vs4.w; }

#pragma unroll 4
    for (int j0 = 0; j0 < cnt; j0 += 4) {
        int j = j0 + g;
        bool ok = j < cnt;
        float t = 0.0f;
        float2 e01, e23, v01, v23;
        if (ok) {
            int n = sn[j];
            uint2 eu = *(const uint2*)(Eb + (size_t)j * D_);
            uint2 ku = *(const uint2*)(Kb + (size_t)n * 512);
            uint2 vu = *(const uint2*)(Vb + (size_t)n * 512);
            e01 = __half22float2(*(__half2*)&eu.x);
            e23 = __half22float2(*(__half2*)&eu.y);
            float2 k01 = __half22float2(*(__half2*)&ku.x);
            float2 k23 = __half22float2(*(__half2*)&ku.y);
            v01 = __half22float2(*(__half2*)&vu.x);
            v23 = __half22float2(*(__half2*)&vu.y);
            t = (q4.x + e01.x) * (k01.x + e01.x) + (q4.y + e01.y) * (k01.y + e01.y)
              + (q4.z + e23.x) * (k23.x + e23.x) + (q4.w + e23.y) * (k23.y + e23.y);
        }
#pragma unroll
        for (int o = 1; o < 8; o <<= 1) t += __shfl_xor_sync(0xffffffffu, t, o);
        if (ok) {
            t *= SCALE_;
            float nm = fmaxf(mx, t);
            float sc = __expf(mx - nm);
            float p  = __expf(t - nm);
            mx = nm;
            sm = sm * sc + p;
            acc.x = fmaf(acc.x, sc, p * (v01.x + e01.x));
            acc.y = fmaf(acc.y, sc, p * (v01.y + e01.y));
            acc.z = fmaf(acc.z, sc, p * (v23.x + e23.x));
            acc.w = fmaf(acc.w, sc, p * (v23.y + e23.y));
        }
    }

#pragma unroll
    for (int o = 8; o < 32; o <<= 1) {
        float pmx = __shfl_xor_sync(0xffffffffu, mx, o);
        float psm = __shfl_xor_sync(0xffffffffu, sm, o);
        float pax = __shfl_xor_sync(0xffffffffu, acc.x, o);
        float pay = __shfl_xor_sync(0xffffffffu, acc.y, o);
        float paz = __shfl_xor_sync(0xffffffffu, acc.z, o);
        float paw = __shfl_xor_sync(0xffffffffu, acc.w, o);
        float nm = fmaxf(mx, pmx);
        float s1 = __expf(mx - nm);
        float s2 = __expf(pmx - nm);
        mx = nm;
        sm = sm * s1 + psm * s2;
        acc.x = acc.x * s1 + pax * s2;
        acc.y = acc.y * s1 + pay * s2;
        acc.z = acc.z * s1 + paz * s2;
        acc.w = acc.w * s1 + paw * s2;
    }
    if (g == 0) {
        float inv = 1.0f / sm;
        float4 r = make_float4(acc.x * inv, acc.y * inv, acc.z * inv, acc.w * inv);
        *(float4*)(ao + h * 32 + d8 * 4) = r;
    }
    __syncthreads();

    float r = machine_emb[(size_t)row * D_ + tid] + bo[tid];
#pragma unroll 8
    for (int k = 0; k < D_; k++) r = fmaf(ao[k], Wo[(size_t)k * D_ + tid], r);
    g_me2[(size_t)row * D_ + tid] = r;

    float s  = warpSum(r);
    float s2 = warpSum(r * r);
    if ((tid & 31) == 0) { red[tid >> 5] = s; red[8 + (tid >> 5)] = s2; }
    __syncthreads();
    float sum = 0.f, sum2 = 0.f;
#pragma unroll
    for (int i = 0; i < 8; i++) { sum += red[i]; sum2 += red[8 + i]; }
    float mu  = sum * (1.0f / D_);
    float var = sum2 * (1.0f / D_) - mu * mu;
    float invs = rsqrtf(var + EPS_);
    g_h16[(size_t)row * D_ + tid] = __float2half((r - mu) * invs * g2[tid] + bn2[tid]);
}

// ---------------- launch ----------------
template <typename T>
static T* symAddr(const void* sym) {
    void* p = nullptr;
    cudaGetSymbolAddress(&p, sym);
    return (T*)p;
}

extern "C" void kernel_launch(void* const* d_in, const int* in_sizes, int n_in,
                              void* d_out, int out_size) {
    const float* machine_emb = (const float*)d_in[0];
    const float* op_emb      = (const float*)d_in[1];
    const float* edge_emb    = (const float*)d_in[2];
    const void*  mask        = d_in[3];
    const float* Wq  = (const float*)d_in[4];
    const float* bq  = (const float*)d_in[5];
    const float* Wk  = (const float*)d_in[6];
    const float* bk  = (const float*)d_in[7];
    const float* Wv  = (const float*)d_in[8];
    const float* bv  = (const float*)d_in[9];
    const float* Wo  = (const float*)d_in[10];
    const float* bo  = (const float*)d_in[11];
    const float* Wks = (const float*)d_in[12];
    const float* bks = (const float*)d_in[13];
    const float* Wvs = (const float*)d_in[14];
    const float* bvs = (const float*)d_in[15];
    const float* We  = (const float*)d_in[16];
    const float* be  = (const float*)d_in[17];
    const float* g1  = (const float*)d_in[18];
    const float* bn1 = (const float*)d_in[19];
    const float* g2  = (const float*)d_in[20];
    const float* bn2 = (const float*)d_in[21];
    const float* gop = (const float*)d_in[22];
    const float* bnop= (const float*)d_in[23];
    const float* Wf1 = (const float*)d_in[24];
    const float* bf1 = (const float*)d_in[25];
    const float* Wf2 = (const float*)d_in[26];
    const float* bf2 = (const float*)d_in[27];
    float* out = (float*)d_out;

    __half* p_mnorm16 = symAddr<__half>(g_mnorm16);
    __half* p_onorm16 = symAddr<__half>(g_onorm16);
    __half* p_Wqkv16  = symAddr<__half>(g_Wqkv16);
    __half* p_Wkv16   = symAddr<__half>(g_Wkv16);
    __half* p_We16    = symAddr<__half>(g_We16);
    __half* p_Wf1_16  = symAddr<__half>(g_Wf1_16);
    __half* p_Wf2_16  = symAddr<__half>(g_Wf2_16);
    __half* p_f1h     = symAddr<__half>(g_f1h);
    __half* p_h16     = symAddr<__half>(g_h16);
    __half* p_kvh     = symAddr<__half>(g_kvh);
    __half* p_Eh      = symAddr<__half>(g_Eh);
    float* p_bqkv = symAddr<float>(g_bqkv);
    float* p_bkv  = symAddr<float>(g_bkv);
    float* p_qkv  = symAddr<float>(g_qkv);
    float* p_f2p  = symAddr<float>(g_f2part);

    static cudaStream_t s1 = nullptr, s2 = nullptr;
    static cudaEvent_t eFork = nullptr, eWe = nullptr, ePack = nullptr, eS1 = nullptr;
    if (!s1) {
        cudaStreamCreateWithFlags(&s1, cudaStreamNonBlocking);
        cudaStreamCreateWithFlags(&s2, cudaStreamNonBlocking);
        cudaEventCreateWithFlags(&eFork, cudaEventDisableTiming);
        cudaEventCreateWithFlags(&eWe,   cudaEventDisableTiming);
        cudaEventCreateWithFlags(&ePack, cudaEventDisableTiming);
        cudaEventCreateWithFlags(&eS1,   cudaEventDisableTiming);
    }

    // ---- fork ----
    cudaEventRecord(eFork, 0);
    cudaStreamWaitEvent(s1, eFork, 0);
    cudaStreamWaitEvent(s2, eFork, 0);

    // branch s2: We packed first (unblocks gather early), then the rest
    pack_we_kernel<<<64, 1024, 0, s2>>>(We);
    cudaEventRecord(eWe, s2);
    pack_kernel<<<320, 1024, 0, s2>>>(Wq, bq, Wks, bks, Wvs, bvs, Wk, bk, Wv, bv,
                                      Wf1, Wf2);
    cudaEventRecord(ePack, s2);

    // branch s1: layernorms -> fused projections
    ln_kernel<<<ROWS_M, 256, 0, s1>>>(machine_emb, g1, bn1, p_mnorm16);
    ln_kernel<<<ROWS_O, 256, 0, s1>>>(op_emb, gop, bnop, p_onorm16);
    cudaStreamWaitEvent(s1, ePack, 0);
    {
        dim3 gQ(ROWS_M / 128, 768 / 128);
        gemm_h<<<gQ, 256, 0, s1>>>(p_mnorm16, p_Wqkv16, p_bqkv, p_qkv, nullptr,
                                   D_, 768, D_, 0, 0);
        dim3 gKV(ROWS_O / 128, 512 / 128);
        gemm_h<<<gKV, 256, 0, s1>>>(p_onorm16, p_Wkv16, p_bkv, nullptr, p_kvh,
                                    D_, 512, D_, 0, FLAG_HALFOUT);
    }
    cudaEventRecord(eS1, s1);

    // main branch: compaction chain -> gathered edge GEMM
    detect_kernel<<<256, 256>>>((const unsigned char*)mask, in_sizes[3]);
    actlist_kernel<<<32, 256>>>(mask);
    prefixfill_kernel<<<ROWS_M, 256>>>();
    cudaStreamWaitEvent(0, eWe, 0);     // gather needs only fp16 We
    {
        dim3 gE(NEDGE / 128, 1);
        gemm_gather<<<gE, 512>>>(edge_emb, p_We16, be, p_Eh);
    }

    // ---- join ----
    cudaStreamWaitEvent(0, eS1, 0);

    attn_kernel<<<ROWS_M, 256>>>(machine_emb, Wo, bo, g2, bn2);

    {
        dim3 gF1(ROWS_M / 128, F_ / 128);
        gemm_h<<<gF1, 256>>>(p_h16, p_Wf1_16, bf1, nullptr, p_f1h,
                             D_, F_, D_, 0, FLAG_RELU | FLAG_HALFOUT);
        dim3 gF2(ROWS_M / 128, D_ / 128, 4);
        gemm_h<<<gF2, 256>>>(p_f1h, p_Wf2_16, bf2, p_f2p, nullptr,
                             F_, D_, F_ / 4, ROWS_M * D_, FLAG_SPLIT);
    }
    f2red_kernel<<<ROWS_M, 256>>>(bf2, out);
}

// round 14
// speedup vs baseline: 1.5950x; 1.0180x over previous
#include <cuda_runtime.h>
#include <cuda_fp16.h>
#include <cstdint>

// ---------------- problem constants ----------------
#define D_      256
#define B_      4
#define M_      64
#define N_      512
#define H_      8
#define F_      1024
#define ROWS_M  256        // B*M
#define ROWS_O  2048       // B*N
#define NEDGE   131072     // B*N*M
#define SCALE_  0.17677669529663687f   // 1/sqrt(32)
#define EPS_    1e-5f
#define BIG_NEG (-1e30f)

#define FLAG_RELU    1
#define FLAG_SPLIT   4
#define FLAG_HALFOUT 8

// ---------------- scratch (device globals; no runtime allocation) ----------------
__device__ __align__(16) __half g_mnorm16[ROWS_M * D_];
__device__ __align__(16) __half g_onorm16[ROWS_O * D_];
__device__ __align__(16) __half g_Wqkv16[D_ * 768];
__device__ __align__(16) __half g_Wkv16 [D_ * 512];
__device__ __align__(16) __half g_We16  [D_ * D_];
__device__ __align__(16) __half g_Wf1_16[D_ * F_];
__device__ __align__(16) __half g_Wf2_16[F_ * D_];
__device__ __align__(16) __half g_f1h   [ROWS_M * F_];
__device__ __align__(16) __half g_h16   [ROWS_M * D_];
__device__ __align__(16) __half g_kvh   [ROWS_O * 512];      // 0:256 k | 256:512 v (fp16)
__device__ __align__(16) __half g_Eh    [(size_t)NEDGE * D_];// compacted projected edges fp16
__device__ float g_bqkv[768];
__device__ float g_bkv [512];
__device__ float g_qkv [ROWS_M * 768];        // 0:256 q | 256:512 ks | 512:768 vs
__device__ float g_me2 [ROWS_M * D_];
__device__ float g_f2part[4 * ROWS_M * D_];
__device__ int   g_actN[ROWS_M * N_];
__device__ int   g_actCnt[ROWS_M];
__device__ int   g_rowStart[ROWS_M + 1];
__device__ int   g_rowIdx[NEDGE];
__device__ int   g_count;
__device__ int   g_flagGt1, g_flagNz;

// ---------------- helpers ----------------
__device__ __forceinline__ float warpSum(float v) {
#pragma unroll
    for (int o = 16; o; o >>= 1) v += __shfl_xor_sync(0xffffffffu, v, o);
    return v;
}
__device__ __forceinline__ uint32_t packh2(float x, float y) {
    __half2 h = __floats2half2_rn(x, y);
    return *reinterpret_cast<uint32_t*>(&h);
}
__device__ __forceinline__ uint2 pack4(float4 v) {
    return make_uint2(packh2(v.x, v.y), packh2(v.z, v.w));
}
__device__ __forceinline__ uint32_t smemAddr(const void* p) {
    return (uint32_t)__cvta_generic_to_shared(p);
}

#define CP16(d, s) asm volatile("cp.async.ca.shared.global [%0], [%1], 16;" :: "r"(d), "l"(s))
#define CPCOMMIT() asm volatile("cp.async.commit_group;")
#define CPWAIT0()  asm volatile("cp.async.wait_group 0;")
#define CPWAIT1()  asm volatile("cp.async.wait_group 1;")

#define LDSM4(r, addr)                                                          \
    asm volatile("ldmatrix.sync.aligned.m8n8.x4.shared.b16 {%0,%1,%2,%3}, [%4];"\
                 : "=r"((r)[0]), "=r"((r)[1]), "=r"((r)[2]), "=r"((r)[3])       \
                 : "r"(addr))
#define LDSM4T(r, addr)                                                         \
    asm volatile("ldmatrix.sync.aligned.m8n8.x4.trans.shared.b16 {%0,%1,%2,%3}, [%4];" \
                 : "=r"((r)[0]), "=r"((r)[1]), "=r"((r)[2]), "=r"((r)[3])       \
                 : "r"(addr))
#define MMA16816(d, a, b0v, b1v)                                                \
    asm volatile("mma.sync.aligned.m16n8k16.row.col.f32.f16.f16.f32 "           \
                 "{%0,%1,%2,%3},{%4,%5,%6,%7},{%8,%9},{%0,%1,%2,%3};"           \
                 : "+f"((d)[0]), "+f"((d)[1]), "+f"((d)[2]), "+f"((d)[3])       \
                 : "r"((a)[0]), "r"((a)[1]), "r"((a)[2]), "r"((a)[3]),          \
                   "r"(b0v), "r"(b1v))

// ---------------- mask preprocessing ----------------
__global__ void detect_kernel(const unsigned char* __restrict__ p, int nbytes) {
    int i = blockIdx.x * blockDim.x + threadIdx.x;
    int stride = gridDim.x * blockDim.x;
    int gt1 = 0, nz = 0;
    for (; i < nbytes; i += stride) {
        unsigned char v = p[i];
        gt1 |= (v > 1);
        nz  |= (v != 0 && (i & 3) != 0);
    }
    if (__any_sync(0xffffffffu, gt1) && (threadIdx.x & 31) == 0) atomicOr(&g_flagGt1, 1);
    if (__any_sync(0xffffffffu, nz)  && (threadIdx.x & 31) == 0) atomicOr(&g_flagNz, 1);
}

__global__ void actlist_kernel(const void* __restrict__ mask) {
    int wid = threadIdx.x >> 5, lane = threadIdx.x & 31;
    int row = blockIdx.x * 8 + wid;
    int b = row >> 6, m = row & 63;
    int mode = g_flagGt1 ? 2 : (g_flagNz ? 1 : 0);
    int base = 0;
#pragma unroll 1
    for (int c = 0; c < 16; c++) {
        int n = c * 32 + lane;
        size_t mi = ((size_t)(b * N_ + n)) * M_ + m;
        bool a;
        if (mode == 2)      a = ((const float*)mask)[mi] != 0.0f;
        else if (mode == 1) a = ((const unsigned char*)mask)[mi] != 0;
        else                a = ((const int*)mask)[mi] != 0;
        unsigned bal = __ballot_sync(0xffffffffu, a);
        if (a) g_actN[row * N_ + base + __popc(bal & ((1u << lane) - 1u))] = n;
        base += __popc(bal);
    }
    if (lane == 0) g_actCnt[row] = base;
}

// Merged prefix + fill; resets mask flags for next replay.
__global__ void prefixfill_kernel() {
    __shared__ int ws[8];
    __shared__ int startS;
    int tid = threadIdx.x;
    int row = blockIdx.x;
    int v = g_actCnt[tid];
    int lane = tid & 31, w = tid >> 5;
    int inc = v;
#pragma unroll
    for (int o = 1; o < 32; o <<= 1) {
        int t = __shfl_up_sync(0xffffffffu, inc, o);
        if (lane >= o) inc += t;
    }
    if (lane == 31) ws[w] = inc;
    __syncthreads();
    int add = 0;
#pragma unroll
    for (int i = 0; i < 8; i++) if (i < w) add += ws[i];
    int excl = inc - v + add;
    if (row == 0) {
        g_rowStart[tid] = excl;
        if (tid == 255) { g_rowStart[256] = excl + v; g_count = excl + v; }
        if (tid == 0) { g_flagGt1 = 0; g_flagNz = 0; }
    }
    if (tid == row) startS = excl;
    __syncthreads();
    int myStart = startS;
    int myCnt = g_actCnt[row];
    int b = row >> 6, m = row & 63;
    for (int i = tid; i < myCnt; i += 256) {
        int n = g_actN[row * N_ + i];
        g_rowIdx[myStart + i] = (b * N_ + n) * M_ + m;
    }
}

// ---------------- weight packing -> fp16 (vectorized, div-free) ----------------
// We packed FIRST (tiny) so the gather GEMM can start early.
__global__ void pack_we_kernel(const float* __restrict__ We) {
    int j = blockIdx.x * 1024 + threadIdx.x;   // 16 blocks: 16384 float4s
    float4 v = ((const float4*)We)[j];
    ((uint2*)g_We16)[j] = pack4(v);
}

__global__ void pack_kernel(const float* __restrict__ Wq,  const float* __restrict__ bq,
                            const float* __restrict__ Wks, const float* __restrict__ bks,
                            const float* __restrict__ Wvs, const float* __restrict__ bvs,
                            const float* __restrict__ Wk,  const float* __restrict__ bk,
                            const float* __restrict__ Wv,  const float* __restrict__ bv,
                            const float* __restrict__ Wf1, const float* __restrict__ Wf2) {
    int stride = gridDim.x * blockDim.x;
    int i0 = blockIdx.x * blockDim.x + threadIdx.x;
    // Wq|Wks|Wvs -> Wqkv (each 256x256: 16384 float4s; out row pitch 768)
    for (int j = i0; j < 16384; j += stride) {
        int k = j >> 6, cv = (j & 63) << 2;
        *(uint2*)&g_Wqkv16[k * 768 + cv]       = pack4(((const float4*)Wq)[j]);
        *(uint2*)&g_Wqkv16[k * 768 + 256 + cv] = pack4(((const float4*)Wks)[j]);
        *(uint2*)&g_Wqkv16[k * 768 + 512 + cv] = pack4(((const float4*)Wvs)[j]);
        *(uint2*)&g_Wkv16[k * 512 + cv]        = pack4(((const float4*)Wk)[j]);
        *(uint2*)&g_Wkv16[k * 512 + 256 + cv]  = pack4(((const float4*)Wv)[j]);
    }
    // Wf1, Wf2 straight copies (65536 float4s each)
    for (int j = i0; j < 65536; j += stride) {
        ((uint2*)g_Wf1_16)[j] = pack4(((const float4*)Wf1)[j]);
        ((uint2*)g_Wf2_16)[j] = pack4(((const float4*)Wf2)[j]);
    }
    if (i0 < 768)
        g_bqkv[i0] = (i0 < 256) ? bq[i0] : (i0 < 512) ? bks[i0 - 256] : bvs[i0 - 512];
    if (i0 < 512)
        g_bkv[i0] = (i0 < 256) ? bk[i0] : bv[i0 - 256];
}

// ---------------- layernorm (fp32 in -> fp16 out) ----------------
__global__ void ln_kernel(const float* __restrict__ x, const float* __restrict__ g,
                          const float* __restrict__ beta, __half* __restrict__ y) {
    __shared__ float red[16];
    int row = blockIdx.x;
    int tid = threadIdx.x;
    float v = x[(size_t)row * D_ + tid];
    float s  = warpSum(v);
    float s2 = warpSum(v * v);
    if ((tid & 31) == 0) { red[tid >> 5] = s; red[8 + (tid >> 5)] = s2; }
    __syncthreads();
    float sum = 0.f, sum2 = 0.f;
#pragma unroll
    for (int i = 0; i < 8; i++) { sum += red[i]; sum2 += red[8 + i]; }
    float mu  = sum * (1.0f / D_);
    float var = sum2 * (1.0f / D_) - mu * mu;
    float inv = rsqrtf(var + EPS_);
    y[(size_t)row * D_ + tid] = __float2half((v - mu) * inv * g[tid] + beta[tid]);
}

// ---------------- fp16/fp16 GEMM, cp.async 3-stage: 128x128 tile, 8 warps ----------
__global__ __launch_bounds__(256)
void gemm_h(const __half* __restrict__ A, const __half* __restrict__ W,
            const float* __restrict__ bias, float* __restrict__ C,
            __half* __restrict__ Ch,
            int K, int N, int kChunk, int partStride, int flags) {
    __shared__ __align__(16) __half A_sh[3][128][40];
    __shared__ __align__(16) __half B_sh[3][32][136];

    int tid = threadIdx.x;
    int r0 = blockIdx.x * 128, n0 = blockIdx.y * 128;
    int kb0 = blockIdx.z * kChunk;
    float* Cout = C + (size_t)blockIdx.z * partStride;

    int a1 = tid, a2 = tid + 256;
    int aR1 = a1 >> 2, aC1 = a1 & 3, aR2 = a2 >> 2, aC2 = a2 & 3;
    const __half* aS1 = A + (size_t)(r0 + aR1) * K + kb0 + aC1 * 8;
    const __half* aS2 = A + (size_t)(r0 + aR2) * K + kb0 + aC2 * 8;
    uint32_t aD1 = smemAddr(&A_sh[0][aR1][aC1 * 8]);
    uint32_t aD2 = smemAddr(&A_sh[0][aR2][aC2 * 8]);
    int bR1 = tid >> 4, bC = tid & 15, bR2 = bR1 + 16;
    const __half* bS1 = W + (size_t)(kb0 + bR1) * N + n0 + bC * 8;
    const __half* bS2 = W + (size_t)(kb0 + bR2) * N + n0 + bC * 8;
    uint32_t bD1 = smemAddr(&B_sh[0][bR1][bC * 8]);
    uint32_t bD2 = smemAddr(&B_sh[0][bR2][bC * 8]);
    const int ABUF = 128 * 40 * 2, BBUF = 32 * 136 * 2;

#define ISSUE(st, koff)                                                         \
    do {                                                                        \
        CP16(aD1 + (st) * ABUF, aS1 + (koff));                                  \
        CP16(aD2 + (st) * ABUF, aS2 + (koff));                                  \
        CP16(bD1 + (st) * BBUF, bS1 + (size_t)(koff) * N);                      \
        CP16(bD2 + (st) * BBUF, bS2 + (size_t)(koff) * N);                      \
    } while (0)

    float acc[2][8][4];
#pragma unroll
    for (int i = 0; i < 2; i++)
#pragma unroll
        for (int j = 0; j < 8; j++)
#pragma unroll
            for (int l = 0; l < 4; l++) acc[i][j][l] = 0.0f;

    int wid = tid >> 5, lane = tid & 31;
    int wm = wid & 3, wn = wid >> 2;
    int lrow = lane & 15, lcol = lane >> 4;
    uint32_t aLd = smemAddr(&A_sh[0][wm * 32 + lrow][lcol * 8]);
    uint32_t bLd = smemAddr(&B_sh[0][lrow][wn * 64 + lcol * 8]);

    int nIter = kChunk / 32;
    ISSUE(0, 0);
    CPCOMMIT();
    if (nIter > 1) ISSUE(1, 32);
    CPCOMMIT();

#pragma unroll 1
    for (int it = 0; it < nIter; it++) {
        CPWAIT1();
        __syncthreads();
        int st = it % 3;
        int nx = it + 2;
        if (nx < nIter) ISSUE(nx % 3, nx * 32);
        CPCOMMIT();
        uint32_t aB = aLd + st * ABUF;
        uint32_t bB = bLd + st * BBUF;
#pragma unroll
        for (int ks = 0; ks < 2; ks++) {
            uint32_t af[2][4];
#pragma unroll
            for (int mf = 0; mf < 2; mf++)
                LDSM4(af[mf], aB + mf * (16 * 80) + ks * 32);
            uint32_t bfm[4][4];
#pragma unroll
            for (int np = 0; np < 4; np++)
                LDSM4T(bfm[np], bB + ks * (16 * 272) + np * 32);
#pragma unroll
            for (int np = 0; np < 4; np++)
#pragma unroll
                for (int hh = 0; hh < 2; hh++) {
                    int nf = np * 2 + hh;
#pragma unroll
                    for (int mf = 0; mf < 2; mf++)
                        MMA16816(acc[mf][nf], af[mf], bfm[np][hh * 2], bfm[np][hh * 2 + 1]);
                }
        }
        __syncthreads();
    }
#undef ISSUE

    int gid = lane >> 2, tig = lane & 3;
#pragma unroll
    for (int mf = 0; mf < 2; mf++) {
#pragma unroll
        for (int half = 0; half < 2; half++) {
            int r = r0 + wm * 32 + mf * 16 + gid + half * 8;
#pragma unroll
            for (int nf = 0; nf < 8; nf++) {
                int cb = n0 + wn * 64 + nf * 8 + tig * 2;
                float v0 = acc[mf][nf][half * 2 + 0];
                float v1 = acc[mf][nf][half * 2 + 1];
                if (!(flags & FLAG_SPLIT)) {
                    v0 += bias[cb];
                    v1 += bias[cb + 1];
                    if (flags & FLAG_RELU) { v0 = fmaxf(v0, 0.f); v1 = fmaxf(v1, 0.f); }
                }
                if (flags & FLAG_HALFOUT) {
                    *(__half2*)&Ch[(size_t)r * N + cb] = __floats2half2_rn(v0, v1);
                } else {
                    Cout[(size_t)r * N + cb]     = v0;
                    Cout[(size_t)r * N + cb + 1] = v1;
                }
            }
        }
    }
}

// ---------------- gathered edge GEMM: 128x256 tile, 512 threads (16 warps) ----------
__global__ __launch_bounds__(512)
void gemm_gather(const float* __restrict__ A, const __half* __restrict__ W16,
                 const float* __restrict__ bias, __half* __restrict__ C) {
    __shared__ __align__(16) __half A_sh[2][128][40];    // 20.0 KB
    __shared__ __align__(16) __half B_sh[2][32][264];    // 33.0 KB
    __shared__ int src[128];

    int tid = threadIdx.x;
    int count = g_count;
    int r0 = blockIdx.x * 128;
    if (r0 >= count) return;
    if (tid < 128) {
        int gidx = r0 + tid;
        src[tid] = g_rowIdx[gidx < count ? gidx : count - 1];
    }
    __syncthreads();
    const int K = D_, N = D_;

    int aR = tid >> 2, aC = tid & 3;
    const float* aPtr = A + (size_t)src[aR] * K + aC * 8;
    int bR = tid >> 5, bC = tid & 31;
    const __half* bS1 = W16 + (size_t)bR * N + bC * 8;
    const __half* bS2 = W16 + (size_t)(bR + 16) * N + bC * 8;
    uint32_t bD1 = smemAddr(&B_sh[0][bR][bC * 8]);
    uint32_t bD2 = smemAddr(&B_sh[0][bR + 16][bC * 8]);
    const int A_BUF = 128 * 40 * 2;
    const int B_BUF = 32 * 264 * 2;

    uint32_t pa[4];
#define LOADA(off)                                                               \
    do {                                                                         \
        float4 t0 = *(const float4*)(aPtr + (off));                              \
        float4 t1 = *(const float4*)(aPtr + (off) + 4);                          \
        pa[0] = packh2(t0.x, t0.y); pa[1] = packh2(t0.z, t0.w);                  \
        pa[2] = packh2(t1.x, t1.y); pa[3] = packh2(t1.z, t1.w);                  \
    } while (0)
#define STOREA(BF) \
    *(uint4*)&A_sh[BF][aR][aC * 8] = make_uint4(pa[0], pa[1], pa[2], pa[3])
#define ISSUEB(st, koff)                                                         \
    do {                                                                         \
        CP16(bD1 + (st) * B_BUF, bS1 + (size_t)(koff) * N);                      \
        CP16(bD2 + (st) * B_BUF, bS2 + (size_t)(koff) * N);                      \
    } while (0)

    float acc[2][8][4];
#pragma unroll
    for (int i = 0; i < 2; i++)
#pragma unroll
        for (int j = 0; j < 8; j++)
#pragma unroll
            for (int l = 0; l < 4; l++) acc[i][j][l] = 0.0f;

    int wid = tid >> 5, lane = tid & 31;
    int wm = wid & 3, wn = wid >> 2;
    int lrow = lane & 15, lcol = lane >> 4;
    uint32_t aLd = smemAddr(&A_sh[0][wm * 32 + lrow][lcol * 8]);
    uint32_t bLd = smemAddr(&B_sh[0][lrow][wn * 64 + lcol * 8]);

    LOADA(0);
    ISSUEB(0, 0);
    CPCOMMIT();
    STOREA(0);
    CPWAIT0();
    __syncthreads();

    int buf = 0;
#pragma unroll 1
    for (int it = 0; it < 8; it++) {
        if (it + 1 < 8) {
            LOADA((it + 1) * 32);
            ISSUEB(buf ^ 1, (it + 1) * 32);
        }
        CPCOMMIT();
        uint32_t aB = aLd + buf * A_BUF;
        uint32_t bB = bLd + buf * B_BUF;
#pragma unroll
        for (int ks = 0; ks < 2; ks++) {
            uint32_t af[2][4];
#pragma unroll
            for (int mf = 0; mf < 2; mf++)
                LDSM4(af[mf], aB + mf * (16 * 80) + ks * 32);
            uint32_t bfm[4][4];
#pragma unroll
            for (int np = 0; np < 4; np++)
                LDSM4T(bfm[np], bB + ks * (16 * 528) + np * 32);
#pragma unroll
            for (int np = 0; np < 4; np++)
#pragma unroll
                for (int hh = 0; hh < 2; hh++) {
                    int nf = np * 2 + hh;
#pragma unroll
                    for (int mf = 0; mf < 2; mf++)
                        MMA16816(acc[mf][nf], af[mf], bfm[np][hh * 2], bfm[np][hh * 2 + 1]);
                }
        }
        if (it + 1 < 8) STOREA(buf ^ 1);
        CPWAIT0();
        __syncthreads();
        buf ^= 1;
    }
#undef LOADA
#undef STOREA
#undef ISSUEB

    int gid = lane >> 2, tig = lane & 3;
#pragma unroll
    for (int mf = 0; mf < 2; mf++) {
#pragma unroll
        for (int half = 0; half < 2; half++) {
            int r = r0 + wm * 32 + mf * 16 + gid + half * 8;
            bool rok = r < count;
#pragma unroll
            for (int nf = 0; nf < 8; nf++) {
                int cb = wn * 64 + nf * 8 + tig * 2;
                if (rok) {
                    float v0 = acc[mf][nf][half * 2 + 0] + bias[cb];
                    float v1 = acc[mf][nf][half * 2 + 1] + bias[cb + 1];
                    *(__half2*)&C[(size_t)r * N + cb] = __floats2half2_rn(v0, v1);
                }
            }
        }
    }
}

// ---------------- split-K reduction for FFN-2 (+bias +residual) -> out ----------------
__global__ void f2red_kernel(const float* __restrict__ bias, float* __restrict__ out) {
    int i = blockIdx.x * 256 + threadIdx.x;
    int c = i & 255;
    out[i] = g_me2[i] + bias[c]
           + g_f2part[i] + g_f2part[65536 + i]
           + g_f2part[131072 + i] + g_f2part[196608 + i];
}

// ---------------- attention: online softmax single pass (+ proj + resid + LN2) ------
__global__ __launch_bounds__(256)
void attn_kernel(const float* __restrict__ machine_emb,
                 const float* __restrict__ Wo, const float* __restrict__ bo,
                 const float* __restrict__ g2, const float* __restrict__ bn2) {
    __shared__ float ao[D_];
    __shared__ int   sn[N_];
    __shared__ float red[16];
    int row = blockIdx.x;
    int b = row >> 6;
    int tid = threadIdx.x, lane = tid & 31, h = tid >> 5;
    int cnt = g_actCnt[row];
    int start = g_rowStart[row];

    for (int i = tid; i < cnt; i += 256) sn[i] = g_actN[row * N_ + i];
    __syncthreads();

    int g = lane >> 3, d8 = lane & 7;
    const float* qkvRow = g_qkv + (size_t)row * 768;
    float4 q4  = ((const float4*)(qkvRow +       h * 32))[d8];
    float4 ks4 = ((const float4*)(qkvRow + 256 + h * 32))[d8];
    float4 vs4 = ((const float4*)(qkvRow + 512 + h * 32))[d8];

    float sSelf = q4.x * ks4.x + q4.y * ks4.y + q4.z * ks4.z + q4.w * ks4.w;
#pragma unroll
    for (int o = 1; o < 8; o <<= 1) sSelf += __shfl_xor_sync(0xffffffffu, sSelf, o);
    sSelf *= SCALE_;

    const __half* Eb = g_Eh  + (size_t)start * D_ + h * 32 + d8 * 4;
    const __half* Kb = g_kvh + (size_t)b * N_ * 512 + h * 32 + d8 * 4;
    const __half* Vb = Kb + 256;

    float mx = (g == 0) ? sSelf : BIG_NEG;
    float sm = (g == 0) ? 1.0f : 0.0f;
    float4 acc = make_float4(0.f, 0.f, 0.f, 0.f);
    if (g == 0) { acc.x = vs4.x; acc.y = vs4.y; acc.z = vs4.z; acc.w = vs4.w; }

#pragma unroll 2
    for (int j0 = 0; j0 < cnt; j0 += 4) {
        int j = j0 + g;
        bool ok = j < cnt;
        float t = 0.0f;
        float2 e01, e23, v01, v23;
        if (ok) {
            int n = sn[j];
            uint2 eu = *(const uint2*)(Eb + (size_t)j * D_);
            uint2 ku = *(const uint2*)(Kb + (size_t)n * 512);
            uint2 vu = *(const uint2*)(Vb + (size_t)n * 512);
            e01 = __half22float2(*(__half2*)&eu.x);
            e23 = __half22float2(*(__half2*)&eu.y);
            float2 k01 = __half22float2(*(__half2*)&ku.x);
            float2 k23 = __half22float2(*(__half2*)&ku.y);
            v01 = __half22float2(*(__half2*)&vu.x);
            v23 = __half22float2(*(__half2*)&vu.y);
            t = (q4.x + e01.x) * (k01.x + e01.x) + (q4.y + e01.y) * (k01.y + e01.y)
              + (q4.z + e23.x) * (k23.x + e23.x) + (q4.w + e23.y) * (k23.y + e23.y);
        }
#pragma unroll
        for (int o = 1; o < 8; o <<= 1) t += __shfl_xor_sync(0xffffffffu, t, o);
        if (ok) {
            t *= SCALE_;
            float nm = fmaxf(mx, t);
            float sc = __expf(mx - nm);
            float p  = __expf(t - nm);
            mx = nm;
            sm = sm * sc + p;
            acc.x = fmaf(acc.x, sc, p * (v01.x + e01.x));
            acc.y = fmaf(acc.y, sc, p * (v01.y + e01.y));
            acc.z = fmaf(acc.z, sc, p * (v23.x + e23.x));
            acc.w = fmaf(acc.w, sc, p * (v23.y + e23.y));
        }
    }

#pragma unroll
    for (int o = 8; o < 32; o <<= 1) {
        float pmx = __shfl_xor_sync(0xffffffffu, mx, o);
        float psm = __shfl_xor_sync(0xffffffffu, sm, o);
        float pax = __shfl_xor_sync(0xffffffffu, acc.x, o);
        float pay = __shfl_xor_sync(0xffffffffu, acc.y, o);
        float paz = __shfl_xor_sync(0xffffffffu, acc.z, o);
        float paw = __shfl_xor_sync(0xffffffffu, acc.w, o);
        float nm = fmaxf(mx, pmx);
        float s1 = __expf(mx - nm);
        float s2 = __expf(pmx - nm);
        mx = nm;
        sm = sm * s1 + psm * s2;
        acc.x = acc.x * s1 + pax * s2;
        acc.y = acc.y * s1 + pay * s2;
        acc.z = acc.z * s1 + paz * s2;
        acc.w = acc.w * s1 + paw * s2;
    }
    if (g == 0) {
        float inv = 1.0f / sm;
        float4 r = make_float4(acc.x * inv, acc.y * inv, acc.z * inv, acc.w * inv);
        *(float4*)(ao + h * 32 + d8 * 4) = r;
    }
    __syncthreads();

    float r = machine_emb[(size_t)row * D_ + tid] + bo[tid];
#pragma unroll 8
    for (int k = 0; k < D_; k++) r = fmaf(ao[k], Wo[(size_t)k * D_ + tid], r);
    g_me2[(size_t)row * D_ + tid] = r;

    float s  = warpSum(r);
    float s2 = warpSum(r * r);
    if ((tid & 31) == 0) { red[tid >> 5] = s; red[8 + (tid >> 5)] = s2; }
    __syncthreads();
    float sum = 0.f, sum2 = 0.f;
#pragma unroll
    for (int i = 0; i < 8; i++) { sum += red[i]; sum2 += red[8 + i]; }
    float mu  = sum * (1.0f / D_);
    float var = sum2 * (1.0f / D_) - mu * mu;
    float invs = rsqrtf(var + EPS_);
    g_h16[(size_t)row * D_ + tid] = __float2half((r - mu) * invs * g2[tid] + bn2[tid]);
}

// ---------------- launch ----------------
template <typename T>
static T* symAddr(const void* sym) {
    void* p = nullptr;
    cudaGetSymbolAddress(&p, sym);
    return (T*)p;
}

extern "C" void kernel_launch(void* const* d_in, const int* in_sizes, int n_in,
                              void* d_out, int out_size) {
    const float* machine_emb = (const float*)d_in[0];
    const float* op_emb      = (const float*)d_in[1];
    const float* edge_emb    = (const float*)d_in[2];
    const void*  mask        = d_in[3];
    const float* Wq  = (const float*)d_in[4];
    const float* bq  = (const float*)d_in[5];
    const float* Wk  = (const float*)d_in[6];
    const float* bk  = (const float*)d_in[7];
    const float* Wv  = (const float*)d_in[8];
    const float* bv  = (const float*)d_in[9];
    const float* Wo  = (const float*)d_in[10];
    const float* bo  = (const float*)d_in[11];
    const float* Wks = (const float*)d_in[12];
    const float* bks = (const float*)d_in[13];
    const float* Wvs = (const float*)d_in[14];
    const float* bvs = (const float*)d_in[15];
    const float* We  = (const float*)d_in[16];
    const float* be  = (const float*)d_in[17];
    const float* g1  = (const float*)d_in[18];
    const float* bn1 = (const float*)d_in[19];
    const float* g2  = (const float*)d_in[20];
    const float* bn2 = (const float*)d_in[21];
    const float* gop = (const float*)d_in[22];
    const float* bnop= (const float*)d_in[23];
    const float* Wf1 = (const float*)d_in[24];
    const float* bf1 = (const float*)d_in[25];
    const float* Wf2 = (const float*)d_in[26];
    const float* bf2 = (const float*)d_in[27];
    float* out = (float*)d_out;

    __half* p_mnorm16 = symAddr<__half>(g_mnorm16);
    __half* p_onorm16 = symAddr<__half>(g_onorm16);
    __half* p_Wqkv16  = symAddr<__half>(g_Wqkv16);
    __half* p_Wkv16   = symAddr<__half>(g_Wkv16);
    __half* p_We16    = symAddr<__half>(g_We16);
    __half* p_Wf1_16  = symAddr<__half>(g_Wf1_16);
    __half* p_Wf2_16  = symAddr<__half>(g_Wf2_16);
    __half* p_f1h     = symAddr<__half>(g_f1h);
    __half* p_h16     = symAddr<__half>(g_h16);
    __half* p_kvh     = symAddr<__half>(g_kvh);
    __half* p_Eh      = symAddr<__half>(g_Eh);
    float* p_bqkv = symAddr<float>(g_bqkv);
    float* p_bkv  = symAddr<float>(g_bkv);
    float* p_qkv  = symAddr<float>(g_qkv);
    float* p_f2p  = symAddr<float>(g_f2part);

    static cudaStream_t s1 = nullptr, s2 = nullptr;
    static cudaEvent_t eFork = nullptr, eWe = nullptr, ePack = nullptr, eS1 = nullptr;
    if (!s1) {
        cudaStreamCreateWithFlags(&s1, cudaStreamNonBlocking);
        cudaStreamCreateWithFlags(&s2, cudaStreamNonBlocking);
        cudaEventCreateWithFlags(&eFork, cudaEventDisableTiming);
        cudaEventCreateWithFlags(&eWe,   cudaEventDisableTiming);
        cudaEventCreateWithFlags(&ePack, cudaEventDisableTiming);
        cudaEventCreateWithFlags(&eS1,   cudaEventDisableTiming);
    }

    // ---- fork ----
    cudaEventRecord(eFork, 0);
    cudaStreamWaitEvent(s1, eFork, 0);
    cudaStreamWaitEvent(s2, eFork, 0);

    // branch s2: We packed first (unblocks gather early), then the rest (fast, vectorized)
    pack_we_kernel<<<16, 1024, 0, s2>>>(We);
    cudaEventRecord(eWe, s2);
    pack_kernel<<<160, 512, 0, s2>>>(Wq, bq, Wks, bks, Wvs, bvs, Wk, bk, Wv, bv,
                                     Wf1, Wf2);
    cudaEventRecord(ePack, s2);

    // branch s1: layernorms -> fused projections
    ln_kernel<<<ROWS_M, 256, 0, s1>>>(machine_emb, g1, bn1, p_mnorm16);
    ln_kernel<<<ROWS_O, 256, 0, s1>>>(op_emb, gop, bnop, p_onorm16);
    cudaStreamWaitEvent(s1, ePack, 0);
    {
        dim3 gQ(ROWS_M / 128, 768 / 128);
        gemm_h<<<gQ, 256, 0, s1>>>(p_mnorm16, p_Wqkv16, p_bqkv, p_qkv, nullptr,
                                   D_, 768, D_, 0, 0);
        dim3 gKV(ROWS_O / 128, 512 / 128);
        gemm_h<<<gKV, 256, 0, s1>>>(p_onorm16, p_Wkv16, p_bkv, nullptr, p_kvh,
                                    D_, 512, D_, 0, FLAG_HALFOUT);
    }
    cudaEventRecord(eS1, s1);

    // main branch: compaction chain -> gathered edge GEMM
    detect_kernel<<<256, 256>>>((const unsigned char*)mask, in_sizes[3]);
    actlist_kernel<<<32, 256>>>(mask);
    prefixfill_kernel<<<ROWS_M, 256>>>();
    cudaStreamWaitEvent(0, eWe, 0);     // gather needs only fp16 We
    {
        dim3 gE(NEDGE / 128, 1);
        gemm_gather<<<gE, 512>>>(edge_emb, p_We16, be, p_Eh);
    }

    // ---- join ----
    cudaStreamWaitEvent(0, eS1, 0);

    attn_kernel<<<ROWS_M, 256>>>(machine_emb, Wo, bo, g2, bn2);

    {
        dim3 gF1(ROWS_M / 128, F_ / 128);
        gemm_h<<<gF1, 256>>>(p_h16, p_Wf1_16, bf1, nullptr, p_f1h,
                             D_, F_, D_, 0, FLAG_RELU | FLAG_HALFOUT);
        dim3 gF2(ROWS_M / 128, D_ / 128, 4);
        gemm_h<<<gF2, 256>>>(p_f1h, p_Wf2_16, bf2, p_f2p, nullptr,
                             F_, D_, F_ / 4, ROWS_M * D_, FLAG_SPLIT);
    }
    f2red_kernel<<<ROWS_M, 256>>>(bf2, out);
}

// round 15
// speedup vs baseline: 1.6263x; 1.0196x over previous
#include <cuda_runtime.h>
#include <cuda_fp16.h>
#include <cstdint>

// ---------------- problem constants ----------------
#define D_      256
#define B_      4
#define M_      64
#define N_      512
#define H_      8
#define F_      1024
#define ROWS_M  256        // B*M
#define ROWS_O  2048       // B*N
#define NEDGE   131072     // B*N*M
#define SCALE_  0.17677669529663687f   // 1/sqrt(32)
#define EPS_    1e-5f
#define BIG_NEG (-1e30f)

#define FLAG_RELU    1
#define FLAG_SPLIT   4
#define FLAG_HALFOUT 8

// ---------------- scratch (device globals; no runtime allocation) ----------------
__device__ __align__(16) __half g_mnorm16[ROWS_M * D_];
__device__ __align__(16) __half g_onorm16[ROWS_O * D_];
__device__ __align__(16) __half g_Wqkv16[D_ * 768];
__device__ __align__(16) __half g_Wkv16 [D_ * 512];
__device__ __align__(16) __half g_We16  [D_ * D_];
__device__ __align__(16) __half g_Wf1_16[D_ * F_];
__device__ __align__(16) __half g_Wf2_16[F_ * D_];
__device__ __align__(16) __half g_f1h   [ROWS_M * F_];
__device__ __align__(16) __half g_h16   [ROWS_M * D_];
__device__ __align__(16) __half g_kvh   [ROWS_O * 512];      // 0:256 k | 256:512 v (fp16)
__device__ __align__(16) __half g_Eh    [(size_t)NEDGE * D_];// compacted projected edges fp16
__device__ float g_bqkv[768];
__device__ float g_bkv [512];
__device__ float g_qkv [ROWS_M * 768];        // 0:256 q | 256:512 ks | 512:768 vs
__device__ float g_me2 [ROWS_M * D_];
__device__ float g_f2part[4 * ROWS_M * D_];
__device__ int   g_actN[ROWS_M * N_];
__device__ int   g_actCnt[ROWS_M];
__device__ int   g_rowStart[ROWS_M + 1];
__device__ int   g_rowIdx[NEDGE];
__device__ int   g_count;
__device__ int   g_flagGt1, g_flagNz;

// ---------------- helpers ----------------
__device__ __forceinline__ float warpSum(float v) {
#pragma unroll
    for (int o = 16; o; o >>= 1) v += __shfl_xor_sync(0xffffffffu, v, o);
    return v;
}
__device__ __forceinline__ uint32_t packh2(float x, float y) {
    __half2 h = __floats2half2_rn(x, y);
    return *reinterpret_cast<uint32_t*>(&h);
}
__device__ __forceinline__ uint2 pack4(float4 v) {
    return make_uint2(packh2(v.x, v.y), packh2(v.z, v.w));
}
__device__ __forceinline__ uint32_t smemAddr(const void* p) {
    return (uint32_t)__cvta_generic_to_shared(p);
}

#define CP16(d, s) asm volatile("cp.async.ca.shared.global [%0], [%1], 16;" :: "r"(d), "l"(s))
#define CPCOMMIT() asm volatile("cp.async.commit_group;")
#define CPWAIT0()  asm volatile("cp.async.wait_group 0;")
#define CPWAIT1()  asm volatile("cp.async.wait_group 1;")

#define LDSM4(r, addr)                                                          \
    asm volatile("ldmatrix.sync.aligned.m8n8.x4.shared.b16 {%0,%1,%2,%3}, [%4];"\
                 : "=r"((r)[0]), "=r"((r)[1]), "=r"((r)[2]), "=r"((r)[3])       \
                 : "r"(addr))
#define LDSM4T(r, addr)                                                         \
    asm volatile("ldmatrix.sync.aligned.m8n8.x4.trans.shared.b16 {%0,%1,%2,%3}, [%4];" \
                 : "=r"((r)[0]), "=r"((r)[1]), "=r"((r)[2]), "=r"((r)[3])       \
                 : "r"(addr))
#define MMA16816(d, a, b0v, b1v)                                                \
    asm volatile("mma.sync.aligned.m16n8k16.row.col.f32.f16.f16.f32 "           \
                 "{%0,%1,%2,%3},{%4,%5,%6,%7},{%8,%9},{%0,%1,%2,%3};"           \
                 : "+f"((d)[0]), "+f"((d)[1]), "+f"((d)[2]), "+f"((d)[3])       \
                 : "r"((a)[0]), "r"((a)[1]), "r"((a)[2]), "r"((a)[3]),          \
                   "r"(b0v), "r"(b1v))

// ---------------- mask preprocessing ----------------
__global__ void detect_kernel(const unsigned char* __restrict__ p, int nbytes) {
    int i = blockIdx.x * blockDim.x + threadIdx.x;
    int stride = gridDim.x * blockDim.x;
    int gt1 = 0, nz = 0;
    for (; i < nbytes; i += stride) {
        unsigned char v = p[i];
        gt1 |= (v > 1);
        nz  |= (v != 0 && (i & 3) != 0);
    }
    if (__any_sync(0xffffffffu, gt1) && (threadIdx.x & 31) == 0) atomicOr(&g_flagGt1, 1);
    if (__any_sync(0xffffffffu, nz)  && (threadIdx.x & 31) == 0) atomicOr(&g_flagNz, 1);
}

__global__ void actlist_kernel(const void* __restrict__ mask) {
    int wid = threadIdx.x >> 5, lane = threadIdx.x & 31;
    int row = blockIdx.x * 8 + wid;
    int b = row >> 6, m = row & 63;
    int mode = g_flagGt1 ? 2 : (g_flagNz ? 1 : 0);
    int base = 0;
#pragma unroll 1
    for (int c = 0; c < 16; c++) {
        int n = c * 32 + lane;
        size_t mi = ((size_t)(b * N_ + n)) * M_ + m;
        bool a;
        if (mode == 2)      a = ((const float*)mask)[mi] != 0.0f;
        else if (mode == 1) a = ((const unsigned char*)mask)[mi] != 0;
        else                a = ((const int*)mask)[mi] != 0;
        unsigned bal = __ballot_sync(0xffffffffu, a);
        if (a) g_actN[row * N_ + base + __popc(bal & ((1u << lane) - 1u))] = n;
        base += __popc(bal);
    }
    if (lane == 0) g_actCnt[row] = base;
}

// Merged prefix + fill; resets mask flags for next replay.
__global__ void prefixfill_kernel() {
    __shared__ int ws[8];
    __shared__ int startS;
    int tid = threadIdx.x;
    int row = blockIdx.x;
    int v = g_actCnt[tid];
    int lane = tid & 31, w = tid >> 5;
    int inc = v;
#pragma unroll
    for (int o = 1; o < 32; o <<= 1) {
        int t = __shfl_up_sync(0xffffffffu, inc, o);
        if (lane >= o) inc += t;
    }
    if (lane == 31) ws[w] = inc;
    __syncthreads();
    int add = 0;
#pragma unroll
    for (int i = 0; i < 8; i++) if (i < w) add += ws[i];
    int excl = inc - v + add;
    if (row == 0) {
        g_rowStart[tid] = excl;
        if (tid == 255) { g_rowStart[256] = excl + v; g_count = excl + v; }
        if (tid == 0) { g_flagGt1 = 0; g_flagNz = 0; }
    }
    if (tid == row) startS = excl;
    __syncthreads();
    int myStart = startS;
    int myCnt = g_actCnt[row];
    int b = row >> 6, m = row & 63;
    for (int i = tid; i < myCnt; i += 256) {
        int n = g_actN[row * N_ + i];
        g_rowIdx[myStart + i] = (b * N_ + n) * M_ + m;
    }
}

// ---------------- weight packing -> fp16 (vectorized, div-free; includes We) --------
__global__ void pack_kernel(const float* __restrict__ Wq,  const float* __restrict__ bq,
                            const float* __restrict__ Wks, const float* __restrict__ bks,
                            const float* __restrict__ Wvs, const float* __restrict__ bvs,
                            const float* __restrict__ Wk,  const float* __restrict__ bk,
                            const float* __restrict__ Wv,  const float* __restrict__ bv,
                            const float* __restrict__ Wf1, const float* __restrict__ Wf2,
                            const float* __restrict__ We) {
    int stride = gridDim.x * blockDim.x;
    int i0 = blockIdx.x * blockDim.x + threadIdx.x;
    // Wq|Wks|Wvs -> Wqkv, Wk|Wv -> Wkv, We straight (each 256x256: 16384 float4s)
    for (int j = i0; j < 16384; j += stride) {
        int k = j >> 6, cv = (j & 63) << 2;
        *(uint2*)&g_Wqkv16[k * 768 + cv]       = pack4(((const float4*)Wq)[j]);
        *(uint2*)&g_Wqkv16[k * 768 + 256 + cv] = pack4(((const float4*)Wks)[j]);
        *(uint2*)&g_Wqkv16[k * 768 + 512 + cv] = pack4(((const float4*)Wvs)[j]);
        *(uint2*)&g_Wkv16[k * 512 + cv]        = pack4(((const float4*)Wk)[j]);
        *(uint2*)&g_Wkv16[k * 512 + 256 + cv]  = pack4(((const float4*)Wv)[j]);
        ((uint2*)g_We16)[j]                    = pack4(((const float4*)We)[j]);
    }
    // Wf1, Wf2 straight copies (65536 float4s each)
    for (int j = i0; j < 65536; j += stride) {
        ((uint2*)g_Wf1_16)[j] = pack4(((const float4*)Wf1)[j]);
        ((uint2*)g_Wf2_16)[j] = pack4(((const float4*)Wf2)[j]);
    }
    if (i0 < 768)
        g_bqkv[i0] = (i0 < 256) ? bq[i0] : (i0 < 512) ? bks[i0 - 256] : bvs[i0 - 512];
    if (i0 < 512)
        g_bkv[i0] = (i0 < 256) ? bk[i0] : bv[i0 - 256];
}

// ---------------- layernorm (fp32 in -> fp16 out) ----------------
__global__ void ln_kernel(const float* __restrict__ x, const float* __restrict__ g,
                          const float* __restrict__ beta, __half* __restrict__ y) {
    __shared__ float red[16];
    int row = blockIdx.x;
    int tid = threadIdx.x;
    float v = x[(size_t)row * D_ + tid];
    float s  = warpSum(v);
    float s2 = warpSum(v * v);
    if ((tid & 31) == 0) { red[tid >> 5] = s; red[8 + (tid >> 5)] = s2; }
    __syncthreads();
    float sum = 0.f, sum2 = 0.f;
#pragma unroll
    for (int i = 0; i < 8; i++) { sum += red[i]; sum2 += red[8 + i]; }
    float mu  = sum * (1.0f / D_);
    float var = sum2 * (1.0f / D_) - mu * mu;
    float inv = rsqrtf(var + EPS_);
    y[(size_t)row * D_ + tid] = __float2half((v - mu) * inv * g[tid] + beta[tid]);
}

// ---------------- fp16/fp16 GEMM, cp.async 3-stage: 128x128 tile, 8 warps ----------
__global__ __launch_bounds__(256)
void gemm_h(const __half* __restrict__ A, const __half* __restrict__ W,
            const float* __restrict__ bias, float* __restrict__ C,
            __half* __restrict__ Ch,
            int K, int N, int kChunk, int partStride, int flags) {
    __shared__ __align__(16) __half A_sh[3][128][40];
    __shared__ __align__(16) __half B_sh[3][32][136];

    int tid = threadIdx.x;
    int r0 = blockIdx.x * 128, n0 = blockIdx.y * 128;
    int kb0 = blockIdx.z * kChunk;
    float* Cout = C + (size_t)blockIdx.z * partStride;

    int a1 = tid, a2 = tid + 256;
    int aR1 = a1 >> 2, aC1 = a1 & 3, aR2 = a2 >> 2, aC2 = a2 & 3;
    const __half* aS1 = A + (size_t)(r0 + aR1) * K + kb0 + aC1 * 8;
    const __half* aS2 = A + (size_t)(r0 + aR2) * K + kb0 + aC2 * 8;
    uint32_t aD1 = smemAddr(&A_sh[0][aR1][aC1 * 8]);
    uint32_t aD2 = smemAddr(&A_sh[0][aR2][aC2 * 8]);
    int bR1 = tid >> 4, bC = tid & 15, bR2 = bR1 + 16;
    const __half* bS1 = W + (size_t)(kb0 + bR1) * N + n0 + bC * 8;
    const __half* bS2 = W + (size_t)(kb0 + bR2) * N + n0 + bC * 8;
    uint32_t bD1 = smemAddr(&B_sh[0][bR1][bC * 8]);
    uint32_t bD2 = smemAddr(&B_sh[0][bR2][bC * 8]);
    const int ABUF = 128 * 40 * 2, BBUF = 32 * 136 * 2;

#define ISSUE(st, koff)                                                         \
    do {                                                                        \
        CP16(aD1 + (st) * ABUF, aS1 + (koff));                                  \
        CP16(aD2 + (st) * ABUF, aS2 + (koff));                                  \
        CP16(bD1 + (st) * BBUF, bS1 + (size_t)(koff) * N);                      \
        CP16(bD2 + (st) * BBUF, bS2 + (size_t)(koff) * N);                      \
    } while (0)

    float acc[2][8][4];
#pragma unroll
    for (int i = 0; i < 2; i++)
#pragma unroll
        for (int j = 0; j < 8; j++)
#pragma unroll
            for (int l = 0; l < 4; l++) acc[i][j][l] = 0.0f;

    int wid = tid >> 5, lane = tid & 31;
    int wm = wid & 3, wn = wid >> 2;
    int lrow = lane & 15, lcol = lane >> 4;
    uint32_t aLd = smemAddr(&A_sh[0][wm * 32 + lrow][lcol * 8]);
    uint32_t bLd = smemAddr(&B_sh[0][lrow][wn * 64 + lcol * 8]);

    int nIter = kChunk / 32;
    ISSUE(0, 0);
    CPCOMMIT();
    if (nIter > 1) ISSUE(1, 32);
    CPCOMMIT();

#pragma unroll 1
    for (int it = 0; it < nIter; it++) {
        CPWAIT1();
        __syncthreads();
        int st = it % 3;
        int nx = it + 2;
        if (nx < nIter) ISSUE(nx % 3, nx * 32);
        CPCOMMIT();
        uint32_t aB = aLd + st * ABUF;
        uint32_t bB = bLd + st * BBUF;
#pragma unroll
        for (int ks = 0; ks < 2; ks++) {
            uint32_t af[2][4];
#pragma unroll
            for (int mf = 0; mf < 2; mf++)
                LDSM4(af[mf], aB + mf * (16 * 80) + ks * 32);
            uint32_t bfm[4][4];
#pragma unroll
            for (int np = 0; np < 4; np++)
                LDSM4T(bfm[np], bB + ks * (16 * 272) + np * 32);
#pragma unroll
            for (int np = 0; np < 4; np++)
#pragma unroll
                for (int hh = 0; hh < 2; hh++) {
                    int nf = np * 2 + hh;
#pragma unroll
                    for (int mf = 0; mf < 2; mf++)
                        MMA16816(acc[mf][nf], af[mf], bfm[np][hh * 2], bfm[np][hh * 2 + 1]);
                }
        }
        __syncthreads();
    }
#undef ISSUE

    int gid = lane >> 2, tig = lane & 3;
#pragma unroll
    for (int mf = 0; mf < 2; mf++) {
#pragma unroll
        for (int half = 0; half < 2; half++) {
            int r = r0 + wm * 32 + mf * 16 + gid + half * 8;
#pragma unroll
            for (int nf = 0; nf < 8; nf++) {
                int cb = n0 + wn * 64 + nf * 8 + tig * 2;
                float v0 = acc[mf][nf][half * 2 + 0];
                float v1 = acc[mf][nf][half * 2 + 1];
                if (!(flags & FLAG_SPLIT)) {
                    v0 += bias[cb];
                    v1 += bias[cb + 1];
                    if (flags & FLAG_RELU) { v0 = fmaxf(v0, 0.f); v1 = fmaxf(v1, 0.f); }
                }
                if (flags & FLAG_HALFOUT) {
                    *(__half2*)&Ch[(size_t)r * N + cb] = __floats2half2_rn(v0, v1);
                } else {
                    Cout[(size_t)r * N + cb]     = v0;
                    Cout[(size_t)r * N + cb + 1] = v1;
                }
            }
        }
    }
}

// ---------------- gathered edge GEMM: 128x256 tile, 512 threads (16 warps) ----------
__global__ __launch_bounds__(512)
void gemm_gather(const float* __restrict__ A, const __half* __restrict__ W16,
                 const float* __restrict__ bias, __half* __restrict__ C) {
    __shared__ __align__(16) __half A_sh[2][128][40];    // 20.0 KB
    __shared__ __align__(16) __half B_sh[2][32][264];    // 33.0 KB
    __shared__ int src[128];

    int tid = threadIdx.x;
    int count = g_count;
    int r0 = blockIdx.x * 128;
    if (r0 >= count) return;
    if (tid < 128) {
        int gidx = r0 + tid;
        src[tid] = g_rowIdx[gidx < count ? gidx : count - 1];
    }
    __syncthreads();
    const int K = D_, N = D_;

    int aR = tid >> 2, aC = tid & 3;
    const float* aPtr = A + (size_t)src[aR] * K + aC * 8;
    int bR = tid >> 5, bC = tid & 31;
    const __half* bS1 = W16 + (size_t)bR * N + bC * 8;
    const __half* bS2 = W16 + (size_t)(bR + 16) * N + bC * 8;
    uint32_t bD1 = smemAddr(&B_sh[0][bR][bC * 8]);
    uint32_t bD2 = smemAddr(&B_sh[0][bR + 16][bC * 8]);
    const int A_BUF = 128 * 40 * 2;
    const int B_BUF = 32 * 264 * 2;

    uint32_t pa[4];
#define LOADA(off)                                                               \
    do {                                                                         \
        float4 t0 = *(const float4*)(aPtr + (off));                              \
        float4 t1 = *(const float4*)(aPtr + (off) + 4);                          \
        pa[0] = packh2(t0.x, t0.y); pa[1] = packh2(t0.z, t0.w);                  \
        pa[2] = packh2(t1.x, t1.y); pa[3] = packh2(t1.z, t1.w);                  \
    } while (0)
#define STOREA(BF) \
    *(uint4*)&A_sh[BF][aR][aC * 8] = make_uint4(pa[0], pa[1], pa[2], pa[3])
#define ISSUEB(st, koff)                                                         \
    do {                                                                         \
        CP16(bD1 + (st) * B_BUF, bS1 + (size_t)(koff) * N);                      \
        CP16(bD2 + (st) * B_BUF, bS2 + (size_t)(koff) * N);                      \
    } while (0)

    float acc[2][8][4];
#pragma unroll
    for (int i = 0; i < 2; i++)
#pragma unroll
        for (int j = 0; j < 8; j++)
#pragma unroll
            for (int l = 0; l < 4; l++) acc[i][j][l] = 0.0f;

    int wid = tid >> 5, lane = tid & 31;
    int wm = wid & 3, wn = wid >> 2;
    int lrow = lane & 15, lcol = lane >> 4;
    uint32_t aLd = smemAddr(&A_sh[0][wm * 32 + lrow][lcol * 8]);
    uint32_t bLd = smemAddr(&B_sh[0][lrow][wn * 64 + lcol * 8]);

    LOADA(0);
    ISSUEB(0, 0);
    CPCOMMIT();
    STOREA(0);
    CPWAIT0();
    __syncthreads();

    int buf = 0;
#pragma unroll 1
    for (int it = 0; it < 8; it++) {
        if (it + 1 < 8) {
            LOADA((it + 1) * 32);
            ISSUEB(buf ^ 1, (it + 1) * 32);
        }
        CPCOMMIT();
        uint32_t aB = aLd + buf * A_BUF;
        uint32_t bB = bLd + buf * B_BUF;
#pragma unroll
        for (int ks = 0; ks < 2; ks++) {
            uint32_t af[2][4];
#pragma unroll
            for (int mf = 0; mf < 2; mf++)
                LDSM4(af[mf], aB + mf * (16 * 80) + ks * 32);
            uint32_t bfm[4][4];
#pragma unroll
            for (int np = 0; np < 4; np++)
                LDSM4T(bfm[np], bB + ks * (16 * 528) + np * 32);
#pragma unroll
            for (int np = 0; np < 4; np++)
#pragma unroll
                for (int hh = 0; hh < 2; hh++) {
                    int nf = np * 2 + hh;
#pragma unroll
                    for (int mf = 0; mf < 2; mf++)
                        MMA16816(acc[mf][nf], af[mf], bfm[np][hh * 2], bfm[np][hh * 2 + 1]);
                }
        }
        if (it + 1 < 8) STOREA(buf ^ 1);
        CPWAIT0();
        __syncthreads();
        buf ^= 1;
    }
#undef LOADA
#undef STOREA
#undef ISSUEB

    int gid = lane >> 2, tig = lane & 3;
#pragma unroll
    for (int mf = 0; mf < 2; mf++) {
#pragma unroll
        for (int half = 0; half < 2; half++) {
            int r = r0 + wm * 32 + mf * 16 + gid + half * 8;
            bool rok = r < count;
#pragma unroll
            for (int nf = 0; nf < 8; nf++) {
                int cb = wn * 64 + nf * 8 + tig * 2;
                if (rok) {
                    float v0 = acc[mf][nf][half * 2 + 0] + bias[cb];
                    float v1 = acc[mf][nf][half * 2 + 1] + bias[cb + 1];
                    *(__half2*)&C[(size_t)r * N + cb] = __floats2half2_rn(v0, v1);
                }
            }
        }
    }
}

// ---------------- split-K reduction for FFN-2 (+bias +residual) -> out ----------------
__global__ void f2red_kernel(const float* __restrict__ bias, float* __restrict__ out) {
    int i = blockIdx.x * 256 + threadIdx.x;
    int c = i & 255;
    out[i] = g_me2[i] + bias[c]
           + g_f2part[i] + g_f2part[65536 + i]
           + g_f2part[131072 + i] + g_f2part[196608 + i];
}

// ---------------- attention: online softmax single pass (+ proj + resid + LN2) ------
__global__ __launch_bounds__(256)
void attn_kernel(const float* __restrict__ machine_emb,
                 const float* __restrict__ Wo, const float* __restrict__ bo,
                 const float* __restrict__ g2, const float* __restrict__ bn2) {
    __shared__ float ao[D_];
    __shared__ int   sn[N_];
    __shared__ float red[16];
    int row = blockIdx.x;
    int b = row >> 6;
    int tid = threadIdx.x, lane = tid & 31, h = tid >> 5;
    int cnt = g_actCnt[row];
    int start = g_rowStart[row];

    for (int i = tid; i < cnt; i += 256) sn[i] = g_actN[row * N_ + i];
    __syncthreads();

    int g = lane >> 3, d8 = lane & 7;
    const float* qkvRow = g_qkv + (size_t)row * 768;
    float4 q4  = ((const float4*)(qkvRow +       h * 32))[d8];
    float4 ks4 = ((const float4*)(qkvRow + 256 + h * 32))[d8];
    float4 vs4 = ((const float4*)(qkvRow + 512 + h * 32))[d8];

    float sSelf = q4.x * ks4.x + q4.y * ks4.y + q4.z * ks4.z + q4.w * ks4.w;
#pragma unroll
    for (int o = 1; o < 8; o <<= 1) sSelf += __shfl_xor_sync(0xffffffffu, sSelf, o);
    sSelf *= SCALE_;

    const __half* Eb = g_Eh  + (size_t)start * D_ + h * 32 + d8 * 4;
    const __half* Kb = g_kvh + (size_t)b * N_ * 512 + h * 32 + d8 * 4;
    const __half* Vb = Kb + 256;

    float mx = (g == 0) ? sSelf : BIG_NEG;
    float sm = (g == 0) ? 1.0f : 0.0f;
    float4 acc = make_float4(0.f, 0.f, 0.f, 0.f);
    if (g == 0) { acc.x = vs4.x; acc.y = vs4.y; acc.z = vs4.z; acc.w = vs4.w; }

#pragma unroll 2
    for (int j0 = 0; j0 < cnt; j0 += 4) {
        int j = j0 + g;
        bool ok = j < cnt;
        float t = 0.0f;
        float2 e01, e23, v01, v23;
        if (ok) {
            int n = sn[j];
            uint2 eu = *(const uint2*)(Eb + (size_t)j * D_);
            uint2 ku = *(const uint2*)(Kb + (size_t)n * 512);
            uint2 vu = *(const uint2*)(Vb + (size_t)n * 512);
            e01 = __half22float2(*(__half2*)&eu.x);
            e23 = __half22float2(*(__half2*)&eu.y);
            float2 k01 = __half22float2(*(__half2*)&ku.x);
            float2 k23 = __half22float2(*(__half2*)&ku.y);
            v01 = __half22float2(*(__half2*)&vu.x);
            v23 = __half22float2(*(__half2*)&vu.y);
            t = (q4.x + e01.x) * (k01.x + e01.x) + (q4.y + e01.y) * (k01.y + e01.y)
              + (q4.z + e23.x) * (k23.x + e23.x) + (q4.w + e23.y) * (k23.y + e23.y);
        }
#pragma unroll
        for (int o = 1; o < 8; o <<= 1) t += __shfl_xor_sync(0xffffffffu, t, o);
        if (ok) {
            t *= SCALE_;
            float nm = fmaxf(mx, t);
            float sc = __expf(mx - nm);
            float p  = __expf(t - nm);
            mx = nm;
            sm = sm * sc + p;
            acc.x = fmaf(acc.x, sc, p * (v01.x + e01.x));
            acc.y = fmaf(acc.y, sc, p * (v01.y + e01.y));
            acc.z = fmaf(acc.z, sc, p * (v23.x + e23.x));
            acc.w = fmaf(acc.w, sc, p * (v23.y + e23.y));
        }
    }

#pragma unroll
    for (int o = 8; o < 32; o <<= 1) {
        float pmx = __shfl_xor_sync(0xffffffffu, mx, o);
        float psm = __shfl_xor_sync(0xffffffffu, sm, o);
        float pax = __shfl_xor_sync(0xffffffffu, acc.x, o);
        float pay = __shfl_xor_sync(0xffffffffu, acc.y, o);
        float paz = __shfl_xor_sync(0xffffffffu, acc.z, o);
        float paw = __shfl_xor_sync(0xffffffffu, acc.w, o);
        float nm = fmaxf(mx, pmx);
        float s1 = __expf(mx - nm);
        float s2 = __expf(pmx - nm);
        mx = nm;
        sm = sm * s1 + psm * s2;
        acc.x = acc.x * s1 + pax * s2;
        acc.y = acc.y * s1 + pay * s2;
        acc.z = acc.z * s1 + paz * s2;
        acc.w = acc.w * s1 + paw * s2;
    }
    if (g == 0) {
        float inv = 1.0f / sm;
        float4 r = make_float4(acc.x * inv, acc.y * inv, acc.z * inv, acc.w * inv);
        *(float4*)(ao + h * 32 + d8 * 4) = r;
    }
    __syncthreads();

    float r = machine_emb[(size_t)row * D_ + tid] + bo[tid];
#pragma unroll 8
    for (int k = 0; k < D_; k++) r = fmaf(ao[k], Wo[(size_t)k * D_ + tid], r);
    g_me2[(size_t)row * D_ + tid] = r;

    float s  = warpSum(r);
    float s2 = warpSum(r * r);
    if ((tid & 31) == 0) { red[tid >> 5] = s; red[8 + (tid >> 5)] = s2; }
    __syncthreads();
    float sum = 0.f, sum2 = 0.f;
#pragma unroll
    for (int i = 0; i < 8; i++) { sum += red[i]; sum2 += red[8 + i]; }
    float mu  = sum * (1.0f / D_);
    float var = sum2 * (1.0f / D_) - mu * mu;
    float invs = rsqrtf(var + EPS_);
    g_h16[(size_t)row * D_ + tid] = __float2half((r - mu) * invs * g2[tid] + bn2[tid]);
}

// ---------------- launch ----------------
template <typename T>
static T* symAddr(const void* sym) {
    void* p = nullptr;
    cudaGetSymbolAddress(&p, sym);
    return (T*)p;
}

extern "C" void kernel_launch(void* const* d_in, const int* in_sizes, int n_in,
                              void* d_out, int out_size) {
    const float* machine_emb = (const float*)d_in[0];
    const float* op_emb      = (const float*)d_in[1];
    const float* edge_emb    = (const float*)d_in[2];
    const void*  mask        = d_in[3];
    const float* Wq  = (const float*)d_in[4];
    const float* bq  = (const float*)d_in[5];
    const float* Wk  = (const float*)d_in[6];
    const float* bk  = (const float*)d_in[7];
    const float* Wv  = (const float*)d_in[8];
    const float* bv  = (const float*)d_in[9];
    const float* Wo  = (const float*)d_in[10];
    const float* bo  = (const float*)d_in[11];
    const float* Wks = (const float*)d_in[12];
    const float* bks = (const float*)d_in[13];
    const float* Wvs = (const float*)d_in[14];
    const float* bvs = (const float*)d_in[15];
    const float* We  = (const float*)d_in[16];
    const float* be  = (const float*)d_in[17];
    const float* g1  = (const float*)d_in[18];
    const float* bn1 = (const float*)d_in[19];
    const float* g2  = (const float*)d_in[20];
    const float* bn2 = (const float*)d_in[21];
    const float* gop = (const float*)d_in[22];
    const float* bnop= (const float*)d_in[23];
    const float* Wf1 = (const float*)d_in[24];
    const float* bf1 = (const float*)d_in[25];
    const float* Wf2 = (const float*)d_in[26];
    const float* bf2 = (const float*)d_in[27];
    float* out = (float*)d_out;

    __half* p_mnorm16 = symAddr<__half>(g_mnorm16);
    __half* p_onorm16 = symAddr<__half>(g_onorm16);
    __half* p_Wqkv16  = symAddr<__half>(g_Wqkv16);
    __half* p_Wkv16   = symAddr<__half>(g_Wkv16);
    __half* p_We16    = symAddr<__half>(g_We16);
    __half* p_Wf1_16  = symAddr<__half>(g_Wf1_16);
    __half* p_Wf2_16  = symAddr<__half>(g_Wf2_16);
    __half* p_f1h     = symAddr<__half>(g_f1h);
    __half* p_h16     = symAddr<__half>(g_h16);
    __half* p_kvh     = symAddr<__half>(g_kvh);
    __half* p_Eh      = symAddr<__half>(g_Eh);
    float* p_bqkv = symAddr<float>(g_bqkv);
    float* p_bkv  = symAddr<float>(g_bkv);
    float* p_qkv  = symAddr<float>(g_qkv);
    float* p_f2p  = symAddr<float>(g_f2part);

    static cudaStream_t s1 = nullptr, s2 = nullptr;
    static cudaEvent_t eFork = nullptr, ePack = nullptr, eS1 = nullptr;
    if (!s1) {
        cudaStreamCreateWithFlags(&s1, cudaStreamNonBlocking);
        cudaStreamCreateWithFlags(&s2, cudaStreamNonBlocking);
        cudaEventCreateWithFlags(&eFork, cudaEventDisableTiming);
        cudaEventCreateWithFlags(&ePack, cudaEventDisableTiming);
        cudaEventCreateWithFlags(&eS1,   cudaEventDisableTiming);
    }

    // ---- fork ----
    cudaEventRecord(eFork, 0);
    cudaStreamWaitEvent(s1, eFork, 0);
    cudaStreamWaitEvent(s2, eFork, 0);

    // branch s2: weight packing (fast, vectorized; includes We)
    pack_kernel<<<160, 512, 0, s2>>>(Wq, bq, Wks, bks, Wvs, bvs, Wk, bk, Wv, bv,
                                     Wf1, Wf2, We);
    cudaEventRecord(ePack, s2);

    // branch s1: layernorms -> fused projections
    ln_kernel<<<ROWS_M, 256, 0, s1>>>(machine_emb, g1, bn1, p_mnorm16);
    ln_kernel<<<ROWS_O, 256, 0, s1>>>(op_emb, gop, bnop, p_onorm16);
    cudaStreamWaitEvent(s1, ePack, 0);
    {
        dim3 gQ(ROWS_M / 128, 768 / 128);
        gemm_h<<<gQ, 256, 0, s1>>>(p_mnorm16, p_Wqkv16, p_bqkv, p_qkv, nullptr,
                                   D_, 768, D_, 0, 0);
        dim3 gKV(ROWS_O / 128, 512 / 128);
        gemm_h<<<gKV, 256, 0, s1>>>(p_onorm16, p_Wkv16, p_bkv, nullptr, p_kvh,
                                    D_, 512, D_, 0, FLAG_HALFOUT);
    }
    cudaEventRecord(eS1, s1);

    // main branch: compaction chain -> gathered edge GEMM (strict ePack gating)
    detect_kernel<<<256, 256>>>((const unsigned char*)mask, in_sizes[3]);
    actlist_kernel<<<32, 256>>>(mask);
    prefixfill_kernel<<<ROWS_M, 256>>>();
    cudaStreamWaitEvent(0, ePack, 0);
    {
        dim3 gE(NEDGE / 128, 1);
        gemm_gather<<<gE, 512>>>(edge_emb, p_We16, be, p_Eh);
    }

    // ---- join ----
    cudaStreamWaitEvent(0, eS1, 0);

    attn_kernel<<<ROWS_M, 256>>>(machine_emb, Wo, bo, g2, bn2);

    {
        dim3 gF1(ROWS_M / 128, F_ / 128);
        gemm_h<<<gF1, 256>>>(p_h16, p_Wf1_16, bf1, nullptr, p_f1h,
                             D_, F_, D_, 0, FLAG_RELU | FLAG_HALFOUT);
        dim3 gF2(ROWS_M / 128, D_ / 128, 4);
        gemm_h<<<gF2, 256>>>(p_f1h, p_Wf2_16, bf2, p_f2p, nullptr,
                             F_, D_, F_ / 4, ROWS_M * D_, FLAG_SPLIT);
    }
    f2red_kernel<<<ROWS_M, 256>>>(bf2, out);
}

// round 16
// speedup vs baseline: 1.7289x; 1.0631x over previous
#include <cuda_runtime.h>
#include <cuda_fp16.h>
#include <cstdint>

// ---------------- problem constants ----------------
#define D_      256
#define B_      4
#define M_      64
#define N_      512
#define H_      8
#define F_      1024
#define ROWS_M  256        // B*M
#define ROWS_O  2048       // B*N
#define NEDGE   131072     // B*N*M
#define SCALE_  0.17677669529663687f   // 1/sqrt(32)
#define EPS_    1e-5f
#define BIG_NEG (-1e30f)

#define FLAG_RELU    1
#define FLAG_SPLIT   4
#define FLAG_HALFOUT 8

// ---------------- scratch (device globals; no runtime allocation) ----------------
__device__ __align__(16) __half g_mnorm16[ROWS_M * D_];
__device__ __align__(16) __half g_onorm16[ROWS_O * D_];
__device__ __align__(16) __half g_Wqkv16[D_ * 768];
__device__ __align__(16) __half g_Wkv16 [D_ * 512];
__device__ __align__(16) __half g_We16  [D_ * D_];
__device__ __align__(16) __half g_Wf1_16[D_ * F_];
__device__ __align__(16) __half g_Wf2_16[F_ * D_];
__device__ __align__(16) __half g_f1h   [ROWS_M * F_];
__device__ __align__(16) __half g_h16   [ROWS_M * D_];
__device__ __align__(16) __half g_kvh   [ROWS_O * 512];      // 0:256 k | 256:512 v (fp16)
__device__ __align__(16) __half g_Eh    [(size_t)NEDGE * D_];// compacted projected edges fp16
__device__ float g_bqkv[768];
__device__ float g_bkv [512];
__device__ float g_qkv [ROWS_M * 768];        // 0:256 q | 256:512 ks | 512:768 vs
__device__ float g_me2 [ROWS_M * D_];
__device__ float g_f2part[4 * ROWS_M * D_];
__device__ int   g_actN[ROWS_M * N_];
__device__ int   g_actCnt[ROWS_M];
__device__ int   g_rowStart[ROWS_M + 1];
__device__ int   g_rowIdx[NEDGE];
__device__ int   g_count;
__device__ int   g_flagGt1, g_flagNz;

// ---------------- helpers ----------------
__device__ __forceinline__ float warpSum(float v) {
#pragma unroll
    for (int o = 16; o; o >>= 1) v += __shfl_xor_sync(0xffffffffu, v, o);
    return v;
}
__device__ __forceinline__ uint32_t packh2(float x, float y) {
    __half2 h = __floats2half2_rn(x, y);
    return *reinterpret_cast<uint32_t*>(&h);
}
__device__ __forceinline__ uint2 pack4(float4 v) {
    return make_uint2(packh2(v.x, v.y), packh2(v.z, v.w));
}
__device__ __forceinline__ uint32_t smemAddr(const void* p) {
    return (uint32_t)__cvta_generic_to_shared(p);
}

#define CP16(d, s) asm volatile("cp.async.ca.shared.global [%0], [%1], 16;" :: "r"(d), "l"(s))
#define CPCOMMIT() asm volatile("cp.async.commit_group;")
#define CPWAIT0()  asm volatile("cp.async.wait_group 0;")
#define CPWAIT1()  asm volatile("cp.async.wait_group 1;")

#define LDSM4(r, addr)                                                          \
    asm volatile("ldmatrix.sync.aligned.m8n8.x4.shared.b16 {%0,%1,%2,%3}, [%4];"\
                 : "=r"((r)[0]), "=r"((r)[1]), "=r"((r)[2]), "=r"((r)[3])       \
                 : "r"(addr))
#define LDSM4T(r, addr)                                                         \
    asm volatile("ldmatrix.sync.aligned.m8n8.x4.trans.shared.b16 {%0,%1,%2,%3}, [%4];" \
                 : "=r"((r)[0]), "=r"((r)[1]), "=r"((r)[2]), "=r"((r)[3])       \
                 : "r"(addr))
#define MMA16816(d, a, b0v, b1v)                                                \
    asm volatile("mma.sync.aligned.m16n8k16.row.col.f32.f16.f16.f32 "           \
                 "{%0,%1,%2,%3},{%4,%5,%6,%7},{%8,%9},{%0,%1,%2,%3};"           \
                 : "+f"((d)[0]), "+f"((d)[1]), "+f"((d)[2]), "+f"((d)[3])       \
                 : "r"((a)[0]), "r"((a)[1]), "r"((a)[2]), "r"((a)[3]),          \
                   "r"(b0v), "r"(b1v))

// ---------------- mask preprocessing ----------------
__global__ void detect_kernel(const unsigned char* __restrict__ p, int nbytes) {
    int i = blockIdx.x * blockDim.x + threadIdx.x;
    int stride = gridDim.x * blockDim.x;
    int gt1 = 0, nz = 0;
    for (; i < nbytes; i += stride) {
        unsigned char v = p[i];
        gt1 |= (v > 1);
        nz  |= (v != 0 && (i & 3) != 0);
    }
    if (__any_sync(0xffffffffu, gt1) && (threadIdx.x & 31) == 0) atomicOr(&g_flagGt1, 1);
    if (__any_sync(0xffffffffu, nz)  && (threadIdx.x & 31) == 0) atomicOr(&g_flagNz, 1);
}

__global__ void actlist_kernel(const void* __restrict__ mask) {
    int wid = threadIdx.x >> 5, lane = threadIdx.x & 31;
    int row = blockIdx.x * 8 + wid;
    int b = row >> 6, m = row & 63;
    int mode = g_flagGt1 ? 2 : (g_flagNz ? 1 : 0);
    int base = 0;
#pragma unroll 1
    for (int c = 0; c < 16; c++) {
        int n = c * 32 + lane;
        size_t mi = ((size_t)(b * N_ + n)) * M_ + m;
        bool a;
        if (mode == 2)      a = ((const float*)mask)[mi] != 0.0f;
        else if (mode == 1) a = ((const unsigned char*)mask)[mi] != 0;
        else                a = ((const int*)mask)[mi] != 0;
        unsigned bal = __ballot_sync(0xffffffffu, a);
        if (a) g_actN[row * N_ + base + __popc(bal & ((1u << lane) - 1u))] = n;
        base += __popc(bal);
    }
    if (lane == 0) g_actCnt[row] = base;
}

// Merged prefix + fill; resets mask flags for next replay.
__global__ void prefixfill_kernel() {
    __shared__ int ws[8];
    __shared__ int startS;
    int tid = threadIdx.x;
    int row = blockIdx.x;
    int v = g_actCnt[tid];
    int lane = tid & 31, w = tid >> 5;
    int inc = v;
#pragma unroll
    for (int o = 1; o < 32; o <<= 1) {
        int t = __shfl_up_sync(0xffffffffu, inc, o);
        if (lane >= o) inc += t;
    }
    if (lane == 31) ws[w] = inc;
    __syncthreads();
    int add = 0;
#pragma unroll
    for (int i = 0; i < 8; i++) if (i < w) add += ws[i];
    int excl = inc - v + add;
    if (row == 0) {
        g_rowStart[tid] = excl;
        if (tid == 255) { g_rowStart[256] = excl + v; g_count = excl + v; }
        if (tid == 0) { g_flagGt1 = 0; g_flagNz = 0; }
    }
    if (tid == row) startS = excl;
    __syncthreads();
    int myStart = startS;
    int myCnt = g_actCnt[row];
    int b = row >> 6, m = row & 63;
    for (int i = tid; i < myCnt; i += 256) {
        int n = g_actN[row * N_ + i];
        g_rowIdx[myStart + i] = (b * N_ + n) * M_ + m;
    }
}

// ---------------- weight packing -> fp16 (vectorized, div-free; includes We) --------
__global__ void pack_kernel(const float* __restrict__ Wq,  const float* __restrict__ bq,
                            const float* __restrict__ Wks, const float* __restrict__ bks,
                            const float* __restrict__ Wvs, const float* __restrict__ bvs,
                            const float* __restrict__ Wk,  const float* __restrict__ bk,
                            const float* __restrict__ Wv,  const float* __restrict__ bv,
                            const float* __restrict__ Wf1, const float* __restrict__ Wf2,
                            const float* __restrict__ We) {
    int stride = gridDim.x * blockDim.x;
    int i0 = blockIdx.x * blockDim.x + threadIdx.x;
    for (int j = i0; j < 16384; j += stride) {
        int k = j >> 6, cv = (j & 63) << 2;
        *(uint2*)&g_Wqkv16[k * 768 + cv]       = pack4(((const float4*)Wq)[j]);
        *(uint2*)&g_Wqkv16[k * 768 + 256 + cv] = pack4(((const float4*)Wks)[j]);
        *(uint2*)&g_Wqkv16[k * 768 + 512 + cv] = pack4(((const float4*)Wvs)[j]);
        *(uint2*)&g_Wkv16[k * 512 + cv]        = pack4(((const float4*)Wk)[j]);
        *(uint2*)&g_Wkv16[k * 512 + 256 + cv]  = pack4(((const float4*)Wv)[j]);
        ((uint2*)g_We16)[j]                    = pack4(((const float4*)We)[j]);
    }
    for (int j = i0; j < 65536; j += stride) {
        ((uint2*)g_Wf1_16)[j] = pack4(((const float4*)Wf1)[j]);
        ((uint2*)g_Wf2_16)[j] = pack4(((const float4*)Wf2)[j]);
    }
    if (i0 < 768)
        g_bqkv[i0] = (i0 < 256) ? bq[i0] : (i0 < 512) ? bks[i0 - 256] : bvs[i0 - 512];
    if (i0 < 512)
        g_bkv[i0] = (i0 < 256) ? bk[i0] : bv[i0 - 256];
}

// ---------------- layernorm (fp32 in -> fp16 out) ----------------
__global__ void ln_kernel(const float* __restrict__ x, const float* __restrict__ g,
                          const float* __restrict__ beta, __half* __restrict__ y) {
    __shared__ float red[16];
    int row = blockIdx.x;
    int tid = threadIdx.x;
    float v = x[(size_t)row * D_ + tid];
    float s  = warpSum(v);
    float s2 = warpSum(v * v);
    if ((tid & 31) == 0) { red[tid >> 5] = s; red[8 + (tid >> 5)] = s2; }
    __syncthreads();
    float sum = 0.f, sum2 = 0.f;
#pragma unroll
    for (int i = 0; i < 8; i++) { sum += red[i]; sum2 += red[8 + i]; }
    float mu  = sum * (1.0f / D_);
    float var = sum2 * (1.0f / D_) - mu * mu;
    float inv = rsqrtf(var + EPS_);
    y[(size_t)row * D_ + tid] = __float2half((v - mu) * inv * g[tid] + beta[tid]);
}

// ---------------- fp16/fp16 GEMM, cp.async 3-stage: 128x128 tile, 8 warps ----------
__global__ __launch_bounds__(256)
void gemm_h(const __half* __restrict__ A, const __half* __restrict__ W,
            const float* __restrict__ bias, float* __restrict__ C,
            __half* __restrict__ Ch,
            int K, int N, int kChunk, int partStride, int flags) {
    __shared__ __align__(16) __half A_sh[3][128][40];
    __shared__ __align__(16) __half B_sh[3][32][136];

    int tid = threadIdx.x;
    int r0 = blockIdx.x * 128, n0 = blockIdx.y * 128;
    int kb0 = blockIdx.z * kChunk;
    float* Cout = C + (size_t)blockIdx.z * partStride;

    int a1 = tid, a2 = tid + 256;
    int aR1 = a1 >> 2, aC1 = a1 & 3, aR2 = a2 >> 2, aC2 = a2 & 3;
    const __half* aS1 = A + (size_t)(r0 + aR1) * K + kb0 + aC1 * 8;
    const __half* aS2 = A + (size_t)(r0 + aR2) * K + kb0 + aC2 * 8;
    uint32_t aD1 = smemAddr(&A_sh[0][aR1][aC1 * 8]);
    uint32_t aD2 = smemAddr(&A_sh[0][aR2][aC2 * 8]);
    int bR1 = tid >> 4, bC = tid & 15, bR2 = bR1 + 16;
    const __half* bS1 = W + (size_t)(kb0 + bR1) * N + n0 + bC * 8;
    const __half* bS2 = W + (size_t)(kb0 + bR2) * N + n0 + bC * 8;
    uint32_t bD1 = smemAddr(&B_sh[0][bR1][bC * 8]);
    uint32_t bD2 = smemAddr(&B_sh[0][bR2][bC * 8]);
    const int ABUF = 128 * 40 * 2, BBUF = 32 * 136 * 2;

#define ISSUE(st, koff)                                                         \
    do {                                                                        \
        CP16(aD1 + (st) * ABUF, aS1 + (koff));                                  \
        CP16(aD2 + (st) * ABUF, aS2 + (koff));                                  \
        CP16(bD1 + (st) * BBUF, bS1 + (size_t)(koff) * N);                      \
        CP16(bD2 + (st) * BBUF, bS2 + (size_t)(koff) * N);                      \
    } while (0)

    float acc[2][8][4];
#pragma unroll
    for (int i = 0; i < 2; i++)
#pragma unroll
        for (int j = 0; j < 8; j++)
#pragma unroll
            for (int l = 0; l < 4; l++) acc[i][j][l] = 0.0f;

    int wid = tid >> 5, lane = tid & 31;
    int wm = wid & 3, wn = wid >> 2;
    int lrow = lane & 15, lcol = lane >> 4;
    uint32_t aLd = smemAddr(&A_sh[0][wm * 32 + lrow][lcol * 8]);
    uint32_t bLd = smemAddr(&B_sh[0][lrow][wn * 64 + lcol * 8]);

    int nIter = kChunk / 32;
    ISSUE(0, 0);
    CPCOMMIT();
    if (nIter > 1) ISSUE(1, 32);
    CPCOMMIT();

#pragma unroll 1
    for (int it = 0; it < nIter; it++) {
        CPWAIT1();
        __syncthreads();
        int st = it % 3;
        int nx = it + 2;
        if (nx < nIter) ISSUE(nx % 3, nx * 32);
        CPCOMMIT();
        uint32_t aB = aLd + st * ABUF;
        uint32_t bB = bLd + st * BBUF;
#pragma unroll
        for (int ks = 0; ks < 2; ks++) {
            uint32_t af[2][4];
#pragma unroll
            for (int mf = 0; mf < 2; mf++)
                LDSM4(af[mf], aB + mf * (16 * 80) + ks * 32);
            uint32_t bfm[4][4];
#pragma unroll
            for (int np = 0; np < 4; np++)
                LDSM4T(bfm[np], bB + ks * (16 * 272) + np * 32);
#pragma unroll
            for (int np = 0; np < 4; np++)
#pragma unroll
                for (int hh = 0; hh < 2; hh++) {
                    int nf = np * 2 + hh;
#pragma unroll
                    for (int mf = 0; mf < 2; mf++)
                        MMA16816(acc[mf][nf], af[mf], bfm[np][hh * 2], bfm[np][hh * 2 + 1]);
                }
        }
        __syncthreads();
    }
#undef ISSUE

    int gid = lane >> 2, tig = lane & 3;
#pragma unroll
    for (int mf = 0; mf < 2; mf++) {
#pragma unroll
        for (int half = 0; half < 2; half++) {
            int r = r0 + wm * 32 + mf * 16 + gid + half * 8;
#pragma unroll
            for (int nf = 0; nf < 8; nf++) {
                int cb = n0 + wn * 64 + nf * 8 + tig * 2;
                float v0 = acc[mf][nf][half * 2 + 0];
                float v1 = acc[mf][nf][half * 2 + 1];
                if (!(flags & FLAG_SPLIT)) {
                    v0 += bias[cb];
                    v1 += bias[cb + 1];
                    if (flags & FLAG_RELU) { v0 = fmaxf(v0, 0.f); v1 = fmaxf(v1, 0.f); }
                }
                if (flags & FLAG_HALFOUT) {
                    *(__half2*)&Ch[(size_t)r * N + cb] = __floats2half2_rn(v0, v1);
                } else {
                    Cout[(size_t)r * N + cb]     = v0;
                    Cout[(size_t)r * N + cb + 1] = v1;
                }
            }
        }
    }
}

// ---------------- gathered edge GEMM: 64x256 tile, 256 threads, 2 CTAs/SM ----------
__global__ __launch_bounds__(256, 2)
void gemm_gather(const float* __restrict__ A, const __half* __restrict__ W16,
                 const float* __restrict__ bias, __half* __restrict__ C) {
    __shared__ __align__(16) __half A_sh[2][64][40];     // 10.0 KB
    __shared__ __align__(16) __half B_sh[2][32][264];    // 33.0 KB
    __shared__ int src[64];

    int tid = threadIdx.x;
    int count = g_count;
    int r0 = blockIdx.x * 64;
    if (r0 >= count) return;
    if (tid < 64) {
        int gidx = r0 + tid;
        src[tid] = g_rowIdx[gidx < count ? gidx : count - 1];
    }
    __syncthreads();
    const int K = D_, N = D_;

    // A: 64 rows x 32 fp32 per iter; thread -> (row = tid>>2, 8-float group tid&3)
    int aR = tid >> 2, aC = tid & 3;
    const float* aPtr = A + (size_t)src[aR] * K + aC * 8;
    // B: 32 rows x 256 fp16 per iter = 1024 x 8-half chunks; 4 per thread
    int bR = tid >> 5, bC = tid & 31;                    // bR 0..7
    const __half* bS0 = W16 + (size_t)bR * N + bC * 8;
    uint32_t bD0 = smemAddr(&B_sh[0][bR][bC * 8]);
    const int A_BUF = 64 * 40 * 2;                       //  5120 B
    const int B_BUF = 32 * 264 * 2;                      // 16896 B

    uint32_t pa[4];
#define LOADA(off)                                                               \
    do {                                                                         \
        float4 t0 = *(const float4*)(aPtr + (off));                              \
        float4 t1 = *(const float4*)(aPtr + (off) + 4);                          \
        pa[0] = packh2(t0.x, t0.y); pa[1] = packh2(t0.z, t0.w);                  \
        pa[2] = packh2(t1.x, t1.y); pa[3] = packh2(t1.z, t1.w);                  \
    } while (0)
#define STOREA(BF) \
    *(uint4*)&A_sh[BF][aR][aC * 8] = make_uint4(pa[0], pa[1], pa[2], pa[3])
#define ISSUEB(st, koff)                                                         \
    do {                                                                         \
        CP16(bD0 + (st) * B_BUF,                 bS0 + (size_t)(koff) * N);      \
        CP16(bD0 + (st) * B_BUF + 8 * 528,       bS0 + (size_t)((koff) + 8) * N);\
        CP16(bD0 + (st) * B_BUF + 16 * 528,      bS0 + (size_t)((koff) + 16) * N);\
        CP16(bD0 + (st) * B_BUF + 24 * 528,      bS0 + (size_t)((koff) + 24) * N);\
    } while (0)

    float acc[2][8][4];
#pragma unroll
    for (int i = 0; i < 2; i++)
#pragma unroll
        for (int j = 0; j < 8; j++)
#pragma unroll
            for (int l = 0; l < 4; l++) acc[i][j][l] = 0.0f;

    int wid = tid >> 5, lane = tid & 31;
    int wm = wid & 1, wn = wid >> 1;                     // 2 x 4 warp grid (32 x 64 tiles)
    int lrow = lane & 15, lcol = lane >> 4;
    uint32_t aLd = smemAddr(&A_sh[0][wm * 32 + lrow][lcol * 8]);
    uint32_t bLd = smemAddr(&B_sh[0][lrow][wn * 64 + lcol * 8]);

    LOADA(0);
    ISSUEB(0, 0);
    CPCOMMIT();
    STOREA(0);
    CPWAIT0();
    __syncthreads();

    int buf = 0;
#pragma unroll 1
    for (int it = 0; it < 8; it++) {
        if (it + 1 < 8) {
            LOADA((it + 1) * 32);
            ISSUEB(buf ^ 1, (it + 1) * 32);
        }
        CPCOMMIT();
        uint32_t aB = aLd + buf * A_BUF;
        uint32_t bB = bLd + buf * B_BUF;
#pragma unroll
        for (int ks = 0; ks < 2; ks++) {
            uint32_t af[2][4];
#pragma unroll
            for (int mf = 0; mf < 2; mf++)
                LDSM4(af[mf], aB + mf * (16 * 80) + ks * 32);
            uint32_t bfm[4][4];
#pragma unroll
            for (int np = 0; np < 4; np++)
                LDSM4T(bfm[np], bB + ks * (16 * 528) + np * 32);
#pragma unroll
            for (int np = 0; np < 4; np++)
#pragma unroll
                for (int hh = 0; hh < 2; hh++) {
                    int nf = np * 2 + hh;
#pragma unroll
                    for (int mf = 0; mf < 2; mf++)
                        MMA16816(acc[mf][nf], af[mf], bfm[np][hh * 2], bfm[np][hh * 2 + 1]);
                }
        }
        if (it + 1 < 8) STOREA(buf ^ 1);
        CPWAIT0();
        __syncthreads();
        buf ^= 1;
    }
#undef LOADA
#undef STOREA
#undef ISSUEB

    int gid = lane >> 2, tig = lane & 3;
#pragma unroll
    for (int mf = 0; mf < 2; mf++) {
#pragma unroll
        for (int half = 0; half < 2; half++) {
            int r = r0 + wm * 32 + mf * 16 + gid + half * 8;
            bool rok = r < count;
#pragma unroll
            for (int nf = 0; nf < 8; nf++) {
                int cb = wn * 64 + nf * 8 + tig * 2;
                if (rok) {
                    float v0 = acc[mf][nf][half * 2 + 0] + bias[cb];
                    float v1 = acc[mf][nf][half * 2 + 1] + bias[cb + 1];
                    *(__half2*)&C[(size_t)r * N + cb] = __floats2half2_rn(v0, v1);
                }
            }
        }
    }
}

// ---------------- split-K reduction for FFN-2 (+bias +residual) -> out ----------------
__global__ void f2red_kernel(const float* __restrict__ bias, float* __restrict__ out) {
    int i = blockIdx.x * 256 + threadIdx.x;
    int c = i & 255;
    out[i] = g_me2[i] + bias[c]
           + g_f2part[i] + g_f2part[65536 + i]
           + g_f2part[131072 + i] + g_f2part[196608 + i];
}

// ---------------- attention: online softmax single pass (+ proj + resid + LN2) ------
__global__ __launch_bounds__(256)
void attn_kernel(const float* __restrict__ machine_emb,
                 const float* __restrict__ Wo, const float* __restrict__ bo,
                 const float* __restrict__ g2, const float* __restrict__ bn2) {
    __shared__ float ao[D_];
    __shared__ int   sn[N_];
    __shared__ float red[16];
    int row = blockIdx.x;
    int b = row >> 6;
    int tid = threadIdx.x, lane = tid & 31, h = tid >> 5;
    int cnt = g_actCnt[row];
    int start = g_rowStart[row];

    for (int i = tid; i < cnt; i += 256) sn[i] = g_actN[row * N_ + i];
    __syncthreads();

    int g = lane >> 3, d8 = lane & 7;
    const float* qkvRow = g_qkv + (size_t)row * 768;
    float4 q4  = ((const float4*)(qkvRow +       h * 32))[d8];
    float4 ks4 = ((const float4*)(qkvRow + 256 + h * 32))[d8];
    float4 vs4 = ((const float4*)(qkvRow + 512 + h * 32))[d8];

    float sSelf = q4.x * ks4.x + q4.y * ks4.y + q4.z * ks4.z + q4.w * ks4.w;
#pragma unroll
    for (int o = 1; o < 8; o <<= 1) sSelf += __shfl_xor_sync(0xffffffffu, sSelf, o);
    sSelf *= SCALE_;

    const __half* Eb = g_Eh  + (size_t)start * D_ + h * 32 + d8 * 4;
    const __half* Kb = g_kvh + (size_t)b * N_ * 512 + h * 32 + d8 * 4;
    const __half* Vb = Kb + 256;

    float mx = (g == 0) ? sSelf : BIG_NEG;
    float sm = (g == 0) ? 1.0f : 0.0f;
    float4 acc = make_float4(0.f, 0.f, 0.f, 0.f);
    if (g == 0) { acc.x = vs4.x; acc.y = vs4.y; acc.z = vs4.z; acc.w = vs4.w; }

#pragma unroll 2
    for (int j0 = 0; j0 < cnt; j0 += 4) {
        int j = j0 + g;
        bool ok = j < cnt;
        float t = 0.0f;
        float2 e01, e23, v01, v23;
        if (ok) {
            int n = sn[j];
            uint2 eu = *(const uint2*)(Eb + (size_t)j * D_);
            uint2 ku = *(const uint2*)(Kb + (size_t)n * 512);
            uint2 vu = *(const uint2*)(Vb + (size_t)n * 512);
            e01 = __half22float2(*(__half2*)&eu.x);
            e23 = __half22float2(*(__half2*)&eu.y);
            float2 k01 = __half22float2(*(__half2*)&ku.x);
            float2 k23 = __half22float2(*(__half2*)&ku.y);
            v01 = __half22float2(*(__half2*)&vu.x);
            v23 = __half22float2(*(__half2*)&vu.y);
            t = (q4.x + e01.x) * (k01.x + e01.x) + (q4.y + e01.y) * (k01.y + e01.y)
              + (q4.z + e23.x) * (k23.x + e23.x) + (q4.w + e23.y) * (k23.y + e23.y);
        }
#pragma unroll
        for (int o = 1; o < 8; o <<= 1) t += __shfl_xor_sync(0xffffffffu, t, o);
        if (ok) {
            t *= SCALE_;
            float nm = fmaxf(mx, t);
            float sc = __expf(mx - nm);
            float p  = __expf(t - nm);
            mx = nm;
            sm = sm * sc + p;
            acc.x = fmaf(acc.x, sc, p * (v01.x + e01.x));
            acc.y = fmaf(acc.y, sc, p * (v01.y + e01.y));
            acc.z = fmaf(acc.z, sc, p * (v23.x + e23.x));
            acc.w = fmaf(acc.w, sc, p * (v23.y + e23.y));
        }
    }

#pragma unroll
    for (int o = 8; o < 32; o <<= 1) {
        float pmx = __shfl_xor_sync(0xffffffffu, mx, o);
        float psm = __shfl_xor_sync(0xffffffffu, sm, o);
        float pax = __shfl_xor_sync(0xffffffffu, acc.x, o);
        float pay = __shfl_xor_sync(0xffffffffu, acc.y, o);
        float paz = __shfl_xor_sync(0xffffffffu, acc.z, o);
        float paw = __shfl_xor_sync(0xffffffffu, acc.w, o);
        float nm = fmaxf(mx, pmx);
        float s1 = __expf(mx - nm);
        float s2 = __expf(pmx - nm);
        mx = nm;
        sm = sm * s1 + psm * s2;
        acc.x = acc.x * s1 + pax * s2;
        acc.y = acc.y * s1 + pay * s2;
        acc.z = acc.z * s1 + paz * s2;
        acc.w = acc.w * s1 + paw * s2;
    }
    if (g == 0) {
        float inv = 1.0f / sm;
        float4 r = make_float4(acc.x * inv, acc.y * inv, acc.z * inv, acc.w * inv);
        *(float4*)(ao + h * 32 + d8 * 4) = r;
    }
    __syncthreads();

    float r = machine_emb[(size_t)row * D_ + tid] + bo[tid];
#pragma unroll 8
    for (int k = 0; k < D_; k++) r = fmaf(ao[k], Wo[(size_t)k * D_ + tid], r);
    g_me2[(size_t)row * D_ + tid] = r;

    float s  = warpSum(r);
    float s2 = warpSum(r * r);
    if ((tid & 31) == 0) { red[tid >> 5] = s; red[8 + (tid >> 5)] = s2; }
    __syncthreads();
    float sum = 0.f, sum2 = 0.f;
#pragma unroll
    for (int i = 0; i < 8; i++) { sum += red[i]; sum2 += red[8 + i]; }
    float mu  = sum * (1.0f / D_);
    float var = sum2 * (1.0f / D_) - mu * mu;
    float invs = rsqrtf(var + EPS_);
    g_h16[(size_t)row * D_ + tid] = __float2half((r - mu) * invs * g2[tid] + bn2[tid]);
}

// ---------------- launch ----------------
template <typename T>
static T* symAddr(const void* sym) {
    void* p = nullptr;
    cudaGetSymbolAddress(&p, sym);
    return (T*)p;
}

extern "C" void kernel_launch(void* const* d_in, const int* in_sizes, int n_in,
                              void* d_out, int out_size) {
    const float* machine_emb = (const float*)d_in[0];
    const float* op_emb      = (const float*)d_in[1];
    const float* edge_emb    = (const float*)d_in[2];
    const void*  mask        = d_in[3];
    const float* Wq  = (const float*)d_in[4];
    const float* bq  = (const float*)d_in[5];
    const float* Wk  = (const float*)d_in[6];
    const float* bk  = (const float*)d_in[7];
    const float* Wv  = (const float*)d_in[8];
    const float* bv  = (const float*)d_in[9];
    const float* Wo  = (const float*)d_in[10];
    const float* bo  = (const float*)d_in[11];
    const float* Wks = (const float*)d_in[12];
    const float* bks = (const float*)d_in[13];
    const float* Wvs = (const float*)d_in[14];
    const float* bvs = (const float*)d_in[15];
    const float* We  = (const float*)d_in[16];
    const float* be  = (const float*)d_in[17];
    const float* g1  = (const float*)d_in[18];
    const float* bn1 = (const float*)d_in[19];
    const float* g2  = (const float*)d_in[20];
    const float* bn2 = (const float*)d_in[21];
    const float* gop = (const float*)d_in[22];
    const float* bnop= (const float*)d_in[23];
    const float* Wf1 = (const float*)d_in[24];
    const float* bf1 = (const float*)d_in[25];
    const float* Wf2 = (const float*)d_in[26];
    const float* bf2 = (const float*)d_in[27];
    float* out = (float*)d_out;

    __half* p_mnorm16 = symAddr<__half>(g_mnorm16);
    __half* p_onorm16 = symAddr<__half>(g_onorm16);
    __half* p_Wqkv16  = symAddr<__half>(g_Wqkv16);
    __half* p_Wkv16   = symAddr<__half>(g_Wkv16);
    __half* p_We16    = symAddr<__half>(g_We16);
    __half* p_Wf1_16  = symAddr<__half>(g_Wf1_16);
    __half* p_Wf2_16  = symAddr<__half>(g_Wf2_16);
    __half* p_f1h     = symAddr<__half>(g_f1h);
    __half* p_h16     = symAddr<__half>(g_h16);
    __half* p_kvh     = symAddr<__half>(g_kvh);
    __half* p_Eh      = symAddr<__half>(g_Eh);
    float* p_bqkv = symAddr<float>(g_bqkv);
    float* p_bkv  = symAddr<float>(g_bkv);
    float* p_qkv  = symAddr<float>(g_qkv);
    float* p_f2p  = symAddr<float>(g_f2part);

    static cudaStream_t s1 = nullptr, s2 = nullptr;
    static cudaEvent_t eFork = nullptr, ePack = nullptr, eS1 = nullptr;
    if (!s1) {
        cudaStreamCreateWithFlags(&s1, cudaStreamNonBlocking);
        cudaStreamCreateWithFlags(&s2, cudaStreamNonBlocking);
        cudaEventCreateWithFlags(&eFork, cudaEventDisableTiming);
        cudaEventCreateWithFlags(&ePack, cudaEventDisableTiming);
        cudaEventCreateWithFlags(&eS1,   cudaEventDisableTiming);
    }

    // ---- fork ----
    cudaEventRecord(eFork, 0);
    cudaStreamWaitEvent(s1, eFork, 0);
    cudaStreamWaitEvent(s2, eFork, 0);

    // branch s2: weight packing (fast, vectorized; includes We)
    pack_kernel<<<160, 512, 0, s2>>>(Wq, bq, Wks, bks, Wvs, bvs, Wk, bk, Wv, bv,
                                     Wf1, Wf2, We);
    cudaEventRecord(ePack, s2);

    // branch s1: layernorms -> fused projections
    ln_kernel<<<ROWS_M, 256, 0, s1>>>(machine_emb, g1, bn1, p_mnorm16);
    ln_kernel<<<ROWS_O, 256, 0, s1>>>(op_emb, gop, bnop, p_onorm16);
    cudaStreamWaitEvent(s1, ePack, 0);
    {
        dim3 gQ(ROWS_M / 128, 768 / 128);
        gemm_h<<<gQ, 256, 0, s1>>>(p_mnorm16, p_Wqkv16, p_bqkv, p_qkv, nullptr,
                                   D_, 768, D_, 0, 0);
        dim3 gKV(ROWS_O / 128, 512 / 128);
        gemm_h<<<gKV, 256, 0, s1>>>(p_onorm16, p_Wkv16, p_bkv, nullptr, p_kvh,
                                    D_, 512, D_, 0, FLAG_HALFOUT);
    }
    cudaEventRecord(eS1, s1);

    // main branch: compaction chain -> gathered edge GEMM (strict ePack gating)
    detect_kernel<<<256, 256>>>((const unsigned char*)mask, in_sizes[3]);
    actlist_kernel<<<32, 256>>>(mask);
    prefixfill_kernel<<<ROWS_M, 256>>>();
    cudaStreamWaitEvent(0, ePack, 0);
    {
        dim3 gE(NEDGE / 64, 1);
        gemm_gather<<<gE, 256>>>(edge_emb, p_We16, be, p_Eh);
    }

    // ---- join ----
    cudaStreamWaitEvent(0, eS1, 0);

    attn_kernel<<<ROWS_M, 256>>>(machine_emb, Wo, bo, g2, bn2);

    {
        dim3 gF1(ROWS_M / 128, F_ / 128);
        gemm_h<<<gF1, 256>>>(p_h16, p_Wf1_16, bf1, nullptr, p_f1h,
                             D_, F_, D_, 0, FLAG_RELU | FLAG_HALFOUT);
        dim3 gF2(ROWS_M / 128, D_ / 128, 4);
        gemm_h<<<gF2, 256>>>(p_f1h, p_Wf2_16, bf2, p_f2p, nullptr,
                             F_, D_, F_ / 4, ROWS_M * D_, FLAG_SPLIT);
    }
    f2red_kernel<<<ROWS_M, 256>>>(bf2, out);
}